// round 2
// baseline (speedup 1.0000x reference)
#include <cuda_runtime.h>

#define BATCH 4
#define NP 30000
#define BN (BATCH*NP)
#define HID 64
#define FD 256
#define R2 4096
#define NT 469   /* ceil(NP/64) */

// ---------------- scratch (no allocation allowed) ----------------
__device__ float g_net[BN*HID];          // 30.7 MB
__device__ int   g_idx[3*BN];            // per-plane bin index
__device__ float g_binsum[BATCH*R2*HID]; // pooling scratch
__device__ float g_bincnt[BATCH*R2];
__device__ float g_c[BN*FD];             // 123 MB
__device__ float g_fea[3*BATCH*R2*FD];   // 50 MB (scatter -> conv1 in; conv2 out)
__device__ float g_feb[3*BATCH*R2*FD];   // conv1 out -> conv2 in
__device__ float g_cnt3[3*BATCH*R2];
__device__ float g_wt[2*2304*FD];        // transposed conv weights [conv][ic*9+kk][oc]

// ---------------- bin indices ----------------
__device__ __forceinline__ int binof(float v){
    const float DEN = (float)(1.0 + 0.1 + 1e-6);
    float w = (v + 0.5f) / DEN;
    w = fminf(fmaxf(w, 0.0f), (float)(1.0 - 1e-6));
    return (int)(w * 64.0f);
}

__global__ void k_idx(const float* __restrict__ p){
    int i = blockIdx.x*256 + threadIdx.x;
    if(i >= BN) return;
    float x = p[i*3+0], y = p[i*3+1], z = p[i*3+2];
    int bx = binof(x), by = binof(y), bz = binof(z);
    g_idx[0*BN+i] = bx + 64*bz;  // xz
    g_idx[1*BN+i] = bx + 64*by;  // xy
    g_idx[2*BN+i] = by + 64*bz;  // yz
}

// ---------------- fused resblock (mode 0: x = p@fc_pos; mode 1/2: x = [net|pooled]) ----------------
#define SM_BLOCK ((64*132 + 64*68 + 128*68 + 64*68)*4)

__global__ void k_block(int mode, const float* __restrict__ p,
                        const float* __restrict__ fcW, const float* __restrict__ fcb,
                        const float* __restrict__ W0, const float* __restrict__ b0,
                        const float* __restrict__ W1, const float* __restrict__ b1,
                        const float* __restrict__ Ws)
{
    extern __shared__ float sm[];
    float* x_s = sm;                  // [64][132]
    float* h_s = x_s + 64*132;        // [64][68]
    float* wA  = h_s + 64*68;         // [128][68]  (W0^T then Ws^T)
    float* w1t = wA  + 128*68;        // [64][68]
    int t = threadIdx.x;
    int b = blockIdx.x / NT, tile = blockIdx.x % NT;
    int pt0 = tile*64;
    int npts = min(64, NP - pt0);

    if(mode == 0){
        for(int e=t; e<64*128; e+=256){
            int pt = e>>7, j = e&127;
            float v = 0.f;
            if(pt < npts){
                int gp = (b*NP + pt0 + pt)*3;
                v = fcb[j] + p[gp]*fcW[j*3] + p[gp+1]*fcW[j*3+1] + p[gp+2]*fcW[j*3+2];
            }
            x_s[pt*132+j] = v;
        }
    } else {
        for(int e=t; e<64*128; e+=256){
            int pt = e>>7, j = e&127;
            float v = 0.f;
            if(pt < npts){
                int gi = b*NP + pt0 + pt;
                v = (j < 64) ? g_net[gi*HID + j]
                             : g_binsum[(b*R2 + g_idx[gi])*HID + (j-64)];
            }
            x_s[pt*132+j] = v;
        }
    }
    for(int e=t; e<64*128; e+=256){ int o=e>>7, k=e&127; wA [k*68+o] = W0[e]; }
    for(int e=t; e<64*64;  e+=256){ int o=e>>6, k=e&63;  w1t[k*68+o] = W1[e]; }
    __syncthreads();

    int o0 = (t & 15)*4;
    int pbase = (t >> 4)*4;

    float acc[4][4];
    #pragma unroll
    for(int i=0;i<4;i++){ acc[i][0]=acc[i][1]=acc[i][2]=acc[i][3]=0.f; }
    #pragma unroll 4
    for(int k=0;k<128;k++){
        float4 w = *(const float4*)&wA[k*68 + o0];
        #pragma unroll
        for(int i=0;i<4;i++){
            float xv = x_s[(pbase+i)*132 + k];
            acc[i][0]+=w.x*xv; acc[i][1]+=w.y*xv; acc[i][2]+=w.z*xv; acc[i][3]+=w.w*xv;
        }
    }
    {
        float c0=b0[o0],c1=b0[o0+1],c2=b0[o0+2],c3=b0[o0+3];
        #pragma unroll
        for(int i=0;i<4;i++){
            float4 hv;
            hv.x=fmaxf(acc[i][0]+c0,0.f); hv.y=fmaxf(acc[i][1]+c1,0.f);
            hv.z=fmaxf(acc[i][2]+c2,0.f); hv.w=fmaxf(acc[i][3]+c3,0.f);
            *(float4*)&h_s[(pbase+i)*68 + o0] = hv;
        }
    }
    __syncthreads();
    for(int e=t; e<64*128; e+=256){ int o=e>>7, k=e&127; wA[k*68+o] = Ws[e]; }

    float acd[4][4];
    #pragma unroll
    for(int i=0;i<4;i++){ acd[i][0]=acd[i][1]=acd[i][2]=acd[i][3]=0.f; }
    #pragma unroll 4
    for(int k=0;k<64;k++){
        float4 w = *(const float4*)&w1t[k*68 + o0];
        #pragma unroll
        for(int i=0;i<4;i++){
            float hv = h_s[(pbase+i)*68 + k];
            acd[i][0]+=w.x*hv; acd[i][1]+=w.y*hv; acd[i][2]+=w.z*hv; acd[i][3]+=w.w*hv;
        }
    }
    {
        float c0=b1[o0],c1=b1[o0+1],c2=b1[o0+2],c3=b1[o0+3];
        #pragma unroll
        for(int i=0;i<4;i++){
            acd[i][0]=fmaxf(acd[i][0]+c0,0.f); acd[i][1]=fmaxf(acd[i][1]+c1,0.f);
            acd[i][2]=fmaxf(acd[i][2]+c2,0.f); acd[i][3]=fmaxf(acd[i][3]+c3,0.f);
        }
    }
    __syncthreads();
    #pragma unroll 4
    for(int k=0;k<128;k++){
        float4 w = *(const float4*)&wA[k*68 + o0];
        #pragma unroll
        for(int i=0;i<4;i++){
            float xv = x_s[(pbase+i)*132 + k];
            acd[i][0]+=w.x*xv; acd[i][1]+=w.y*xv; acd[i][2]+=w.z*xv; acd[i][3]+=w.w*xv;
        }
    }
    #pragma unroll
    for(int i=0;i<4;i++){
        int pt = pbase+i;
        if(pt < npts){
            float4 ov = make_float4(acd[i][0],acd[i][1],acd[i][2],acd[i][3]);
            *(float4*)&g_net[(b*NP + pt0 + pt)*HID + o0] = ov;
        }
    }
}

// ---------------- pooling scatter / normalize ----------------
__global__ void k_scatter_net(){
    int i = blockIdx.x*256 + threadIdx.x;
    if(i >= BN*HID) return;
    int ch = i & 63, pt = i >> 6;
    int b = pt / NP;
    int bin = g_idx[pt];
    atomicAdd(&g_binsum[(b*R2 + bin)*HID + ch], g_net[i]);
    if(ch == 0) atomicAdd(&g_bincnt[b*R2 + bin], 1.0f);
}

__global__ void k_poolnorm(){
    int i = blockIdx.x*256 + threadIdx.x;
    if(i >= BATCH*R2*HID) return;
    g_binsum[i] /= fmaxf(g_bincnt[i>>6], 1.0f);
}

// ---------------- fc_c: [64] -> [256] ----------------
#define SM_FCC ((64*68 + 64*260)*4)
__global__ void k_fc_c(const float* __restrict__ Wc, const float* __restrict__ bc){
    extern __shared__ float sm[];
    float* x_s = sm;             // [64][68]
    float* wct = sm + 64*68;     // [64][260]
    int t = threadIdx.x;
    int b = blockIdx.x / NT, tile = blockIdx.x % NT;
    int pt0 = tile*64, npts = min(64, NP - pt0);
    for(int e=t; e<64*64; e+=256){
        int pt = e>>6, k = e&63;
        x_s[pt*68+k] = (pt < npts) ? g_net[(b*NP+pt0+pt)*HID + k] : 0.f;
    }
    for(int e=t; e<256*64; e+=256){
        int o = e>>6, k = e&63;
        wct[k*260 + o] = Wc[e];
    }
    __syncthreads();
    int og = t & 15, pbase = (t>>4)*4;
    for(int oc=0; oc<4; oc++){
        int o0 = oc*64 + og*4;
        float acc[4][4];
        #pragma unroll
        for(int i=0;i<4;i++){ acc[i][0]=acc[i][1]=acc[i][2]=acc[i][3]=0.f; }
        #pragma unroll 4
        for(int k=0;k<64;k++){
            float4 w = *(const float4*)&wct[k*260 + o0];
            #pragma unroll
            for(int i=0;i<4;i++){
                float xv = x_s[(pbase+i)*68 + k];
                acc[i][0]+=w.x*xv; acc[i][1]+=w.y*xv; acc[i][2]+=w.z*xv; acc[i][3]+=w.w*xv;
            }
        }
        float c0=bc[o0],c1=bc[o0+1],c2=bc[o0+2],c3=bc[o0+3];
        #pragma unroll
        for(int i=0;i<4;i++){
            int pt = pbase+i;
            if(pt < npts){
                float4 ov = make_float4(acc[i][0]+c0, acc[i][1]+c1, acc[i][2]+c2, acc[i][3]+c3);
                *(float4*)&g_c[(b*NP+pt0+pt)*FD + o0] = ov;
            }
        }
    }
}

// ---------------- scatter c to 3 planes + normalize ----------------
__global__ void k_scatter_c(){
    int i = blockIdx.x*256 + threadIdx.x;
    if(i >= 3*BN*FD) return;
    int ch = i & 255, r = i >> 8;
    int pl = r / BN, pt = r - pl*BN;
    int b = pt / NP;
    int bin = g_idx[pl*BN + pt];
    atomicAdd(&g_fea[((pl*BATCH+b)*R2 + bin)*FD + ch], g_c[pt*FD + ch]);
    if(ch == 0) atomicAdd(&g_cnt3[(pl*BATCH+b)*R2 + bin], 1.0f);
}

__global__ void k_cnorm(){
    int i = blockIdx.x*256 + threadIdx.x;
    if(i >= 3*BATCH*R2*FD) return;
    g_fea[i] /= fmaxf(g_cnt3[i>>8], 1.0f);
}

// ---------------- conv weight transpose: W[oc][ic][3][3] -> g_wt[conv][ic*9+kk][oc] ----------------
__global__ void k_wtrans(const float* __restrict__ Wa, const float* __restrict__ Wb){
    int i = blockIdx.x*256 + threadIdx.x;
    if(i >= 2*256*2304) return;
    int c = i / (256*2304);
    int rem = i - c*256*2304;
    int oc = rem / 2304, icq = rem - oc*2304;
    const float* W = c ? Wb : Wa;
    g_wt[c*2304*FD + icq*FD + oc] = W[rem];
}

// ---------------- 3x3 conv 256->256 (+bias, relu), NHWC implicit GEMM, f32x2 packed ----------------
// f32x2 lanes carry even/odd input-channel partial sums; summed in epilogue.
#define SM_CONV ((264*18 + 72*128)*4)

__device__ __forceinline__ void fma2(unsigned long long& d,
                                     unsigned long long a, unsigned long long b){
    asm("fma.rn.f32x2 %0, %1, %2, %0;" : "+l"(d) : "l"(a), "l"(b));
}

__global__ void k_conv(const float* __restrict__ in, float* __restrict__ out,
                       const float* __restrict__ wt, const float* __restrict__ bias)
{
    extern __shared__ float sm[];
    float* in_s = sm;              // [264][18] : 4 rows x 66 cols, stride 18 (8B-aligned ch pairs)
    float* w_s  = sm + 264*18;     // [72][128] : (kk*8+il2) x {oc}x{par} interleaved pairs
    int t = threadIdx.x;
    int ocb = blockIdx.x & 3;
    int r = blockIdx.x >> 2;
    int rp = r & 31;
    int pb = r >> 5;               // plane*BATCH + b, 0..11
    const float* inp  = in  + pb*R2*FD;
    float*       outp = out + pb*R2*FD;
    int y0 = rp*2;
    int og = t & 15, pxg = t >> 4;
    int tr = pxg >> 3, c0 = (pxg & 7)*8;

    unsigned long long acc2[8][4];
    #pragma unroll
    for(int i=0;i<8;i++){ acc2[i][0]=acc2[i][1]=acc2[i][2]=acc2[i][3]=0ULL; }

    for(int ic0=0; ic0<FD; ic0+=16){
        __syncthreads();
        // input patch: rows y0-1..y0+2, cols -1..64, 16 channels (zero pad at border)
        for(int e=t; e<1056; e+=256){
            int pos = e>>2, j = e&3;
            int rr = pos/66, cc = pos - rr*66;
            int yy = y0 + rr - 1, xx = cc - 1;
            float4 v = make_float4(0.f,0.f,0.f,0.f);
            if(yy >= 0 && yy < 64 && (unsigned)xx < 64u)
                v = *(const float4*)&inp[(yy*64+xx)*FD + ic0 + j*4];
            float* d = &in_s[pos*18 + j*4];
            d[0]=v.x; d[1]=v.y; d[2]=v.z; d[3]=v.w;
        }
        // weight slice: interleave il-pairs -> w_s[(kk*8+il2)*128 + oc*2 + (il&1)]
        for(int e=t; e<2304; e+=256){
            int q = e>>4, j = e&15;           // q in 0..143 = il*9+kk, j = float4 within 64 oc
            int il = q/9, kk = q - il*9;
            int il2 = il>>1, par = il&1;
            float4 w = *(const float4*)&wt[((ic0+il)*9 + kk)*FD + ocb*64 + j*4];
            float* d = &w_s[(kk*8+il2)*128 + j*8 + par];
            d[0]=w.x; d[2]=w.y; d[4]=w.z; d[6]=w.w;
        }
        __syncthreads();
        #pragma unroll
        for(int kk=0; kk<9; kk++){
            int ky = kk/3, kx = kk - ky*3;
            const float* in_base = &in_s[((tr+ky)*66 + c0 + kx)*18];
            const float* wbase   = &w_s[kk*8*128 + og*8];
            #pragma unroll 2
            for(int il2=0; il2<8; il2++){
                unsigned long long xp[8];
                #pragma unroll
                for(int px=0; px<8; px++)
                    xp[px] = *(const unsigned long long*)(in_base + px*18 + il2*2);
                ulonglong2 wA = *(const ulonglong2*)(wbase + il2*128);
                ulonglong2 wB = *(const ulonglong2*)(wbase + il2*128 + 4);
                #pragma unroll
                for(int px=0; px<8; px++){
                    fma2(acc2[px][0], xp[px], wA.x);
                    fma2(acc2[px][1], xp[px], wA.y);
                    fma2(acc2[px][2], xp[px], wB.x);
                    fma2(acc2[px][3], xp[px], wB.y);
                }
            }
        }
    }
    int o0 = ocb*64 + og*4;
    float b0v=bias[o0], b1v=bias[o0+1], b2v=bias[o0+2], b3v=bias[o0+3];
    int y = y0 + tr;
    #pragma unroll
    for(int px=0; px<8; px++){
        int x = c0 + px;
        float lo, hi;
        float4 ov;
        asm("mov.b64 {%0,%1}, %2;" : "=f"(lo), "=f"(hi) : "l"(acc2[px][0]));
        ov.x = fmaxf(lo+hi+b0v, 0.f);
        asm("mov.b64 {%0,%1}, %2;" : "=f"(lo), "=f"(hi) : "l"(acc2[px][1]));
        ov.y = fmaxf(lo+hi+b1v, 0.f);
        asm("mov.b64 {%0,%1}, %2;" : "=f"(lo), "=f"(hi) : "l"(acc2[px][2]));
        ov.z = fmaxf(lo+hi+b2v, 0.f);
        asm("mov.b64 {%0,%1}, %2;" : "=f"(lo), "=f"(hi) : "l"(acc2[px][3]));
        ov.w = fmaxf(lo+hi+b3v, 0.f);
        *(float4*)&outp[(y*64+x)*FD + o0] = ov;
    }
}

// ---------------- bilinear grid sample over 3 planes, accumulate ----------------
__global__ void k_sample(const float* __restrict__ query, float* __restrict__ out){
    int gid = blockIdx.x*256 + threadIdx.x;
    int w = gid >> 5, lane = gid & 31;
    if(w >= BN) return;
    int b = w / NP;
    float q0 = query[w*3+0], q1 = query[w*3+1], q2 = query[w*3+2];
    float a0[4] = {0,0,0,0}, a1[4] = {0,0,0,0};
    #pragma unroll
    for(int pl=0; pl<3; pl++){
        float qa = (pl==2) ? q1 : q0;       // coord0 -> W
        float qb = (pl==1) ? q1 : q2;       // coord1 -> H
        float gx = qa*2.0f - 1.0f, gy = qb*2.0f - 1.0f;
        float x = ((gx + 1.0f)*64.0f - 1.0f)*0.5f;
        float y = ((gy + 1.0f)*64.0f - 1.0f)*0.5f;
        x = fminf(fmaxf(x, 0.0f), 63.0f);
        y = fminf(fmaxf(y, 0.0f), 63.0f);
        float x0f = floorf(x), y0f = floorf(y);
        int x0 = (int)x0f, y0 = (int)y0f;
        int x1 = min(x0+1, 63), y1 = min(y0+1, 63);
        float wx = x - x0f, wy = y - y0f;
        const float* f = &g_fea[(pl*BATCH + b)*R2*FD];
        float ww[4] = {(1.f-wx)*(1.f-wy), wx*(1.f-wy), (1.f-wx)*wy, wx*wy};
        int pix[4] = {y0*64+x0, y0*64+x1, y1*64+x0, y1*64+x1};
        #pragma unroll
        for(int tp=0; tp<4; tp++){
            const float* base = f + pix[tp]*FD;
            float4 v0 = *(const float4*)&base[lane*4];
            float4 v1 = *(const float4*)&base[128 + lane*4];
            float g = ww[tp];
            a0[0]+=g*v0.x; a0[1]+=g*v0.y; a0[2]+=g*v0.z; a0[3]+=g*v0.w;
            a1[0]+=g*v1.x; a1[1]+=g*v1.y; a1[2]+=g*v1.z; a1[3]+=g*v1.w;
        }
    }
    float* ob = &out[w*FD];
    *(float4*)&ob[lane*4]       = make_float4(a0[0],a0[1],a0[2],a0[3]);
    *(float4*)&ob[128+lane*4]   = make_float4(a1[0],a1[1],a1[2],a1[3]);
}

// ---------------- launch ----------------
extern "C" void kernel_launch(void* const* d_in, const int* in_sizes, int n_in,
                              void* d_out, int out_size)
{
    const float* p    = (const float*)d_in[0];
    const float* qry  = (const float*)d_in[1];
    const float* fcW  = (const float*)d_in[2];
    const float* fcb  = (const float*)d_in[3];
    const float* W0   = (const float*)d_in[4];
    const float* b0   = (const float*)d_in[5];
    const float* W1   = (const float*)d_in[6];
    const float* b1   = (const float*)d_in[7];
    const float* Ws   = (const float*)d_in[8];
    const float* Wc   = (const float*)d_in[9];
    const float* bc   = (const float*)d_in[10];
    const float* C1W  = (const float*)d_in[11];
    const float* C1b  = (const float*)d_in[12];
    const float* C2W  = (const float*)d_in[13];
    const float* C2b  = (const float*)d_in[14];
    float* out = (float*)d_out;

    cudaFuncSetAttribute(k_block, cudaFuncAttributeMaxDynamicSharedMemorySize, SM_BLOCK);
    cudaFuncSetAttribute(k_fc_c,  cudaFuncAttributeMaxDynamicSharedMemorySize, SM_FCC);
    cudaFuncSetAttribute(k_conv,  cudaFuncAttributeMaxDynamicSharedMemorySize, SM_CONV);

    void *binsum_p, *bincnt_p, *fea_p, *cnt3_p, *feb_p, *wt_p;
    cudaGetSymbolAddress(&binsum_p, g_binsum);
    cudaGetSymbolAddress(&bincnt_p, g_bincnt);
    cudaGetSymbolAddress(&fea_p,    g_fea);
    cudaGetSymbolAddress(&feb_p,    g_feb);
    cudaGetSymbolAddress(&cnt3_p,   g_cnt3);
    cudaGetSymbolAddress(&wt_p,     g_wt);

    k_idx<<<(BN+255)/256, 256>>>(p);
    k_block<<<BATCH*NT, 256, SM_BLOCK>>>(0, p, fcW, fcb, W0, b0, W1, b1, Ws);

    for(int it=1; it<=2; it++){
        cudaMemsetAsync(binsum_p, 0, (size_t)BATCH*R2*HID*4);
        cudaMemsetAsync(bincnt_p, 0, (size_t)BATCH*R2*4);
        k_scatter_net<<<(BN*HID+255)/256, 256>>>();
        k_poolnorm<<<(BATCH*R2*HID+255)/256, 256>>>();
        k_block<<<BATCH*NT, 256, SM_BLOCK>>>(it, p, fcW, fcb,
                 W0 + it*HID*128, b0 + it*HID, W1 + it*HID*HID, b1 + it*HID, Ws + it*HID*128);
    }

    k_fc_c<<<BATCH*NT, 256, SM_FCC>>>(Wc, bc);

    cudaMemsetAsync(fea_p,  0, (size_t)3*BATCH*R2*FD*4);
    cudaMemsetAsync(cnt3_p, 0, (size_t)3*BATCH*R2*4);
    k_scatter_c<<<(3*BN*FD)/256, 256>>>();
    k_cnorm<<<(3*BATCH*R2*FD)/256, 256>>>();

    k_wtrans<<<(2*256*2304)/256, 256>>>(C1W, C2W);

    k_conv<<<12*32*4, 256, SM_CONV>>>((const float*)fea_p, (float*)feb_p,
                                      (const float*)wt_p,                 C1b);
    k_conv<<<12*32*4, 256, SM_CONV>>>((const float*)feb_p, (float*)fea_p,
                                      (const float*)wt_p + 2304*FD,       C2b);

    k_sample<<<(BN*32)/256, 256>>>(qry, out);
}

// round 3
// speedup vs baseline: 2.1568x; 2.1568x over previous
#include <cuda_runtime.h>

#define BATCH 4
#define NP 30000
#define BN (BATCH*NP)
#define HID 64
#define FD 256
#define R2 4096
#define NT 469   /* ceil(NP/64) */

// ---------------- scratch (no allocation allowed) ----------------
__device__ float g_net[BN*HID];          // 30.7 MB
__device__ int   g_idx[3*BN];            // per-plane bin index
__device__ float g_binsum[BATCH*R2*HID]; // pooling scratch
__device__ float g_bincnt[BATCH*R2];
__device__ float g_c[BN*FD];             // 123 MB
__device__ float g_fea[3*BATCH*R2*FD];   // 50 MB (scatter -> conv1 in; conv2 out)
__device__ float g_feb[3*BATCH*R2*FD];   // conv1 out -> conv2 in
__device__ float g_cnt3[3*BATCH*R2];
__device__ float g_wt[2*2304*FD];        // tf32 weights [conv][ch(32)][kk(9)][oc(256)][icp(8)]

// ---------------- bin indices ----------------
__device__ __forceinline__ int binof(float v){
    const float DEN = (float)(1.0 + 0.1 + 1e-6);
    float w = (v + 0.5f) / DEN;
    w = fminf(fmaxf(w, 0.0f), (float)(1.0 - 1e-6));
    return (int)(w * 64.0f);
}

__global__ void k_idx(const float* __restrict__ p){
    int i = blockIdx.x*256 + threadIdx.x;
    if(i >= BN) return;
    float x = p[i*3+0], y = p[i*3+1], z = p[i*3+2];
    int bx = binof(x), by = binof(y), bz = binof(z);
    g_idx[0*BN+i] = bx + 64*bz;  // xz
    g_idx[1*BN+i] = bx + 64*by;  // xy
    g_idx[2*BN+i] = by + 64*bz;  // yz
}

// ---------------- fused resblock (mode 0: x = p@fc_pos; mode 1/2: x = [net|pooled]) ----------------
#define SM_BLOCK ((64*132 + 64*68 + 128*68 + 64*68)*4)

__global__ void k_block(int mode, const float* __restrict__ p,
                        const float* __restrict__ fcW, const float* __restrict__ fcb,
                        const float* __restrict__ W0, const float* __restrict__ b0,
                        const float* __restrict__ W1, const float* __restrict__ b1,
                        const float* __restrict__ Ws)
{
    extern __shared__ float sm[];
    float* x_s = sm;                  // [64][132]
    float* h_s = x_s + 64*132;        // [64][68]
    float* wA  = h_s + 64*68;         // [128][68]  (W0^T then Ws^T)
    float* w1t = wA  + 128*68;        // [64][68]
    int t = threadIdx.x;
    int b = blockIdx.x / NT, tile = blockIdx.x % NT;
    int pt0 = tile*64;
    int npts = min(64, NP - pt0);

    if(mode == 0){
        for(int e=t; e<64*128; e+=256){
            int pt = e>>7, j = e&127;
            float v = 0.f;
            if(pt < npts){
                int gp = (b*NP + pt0 + pt)*3;
                v = fcb[j] + p[gp]*fcW[j*3] + p[gp+1]*fcW[j*3+1] + p[gp+2]*fcW[j*3+2];
            }
            x_s[pt*132+j] = v;
        }
    } else {
        for(int e=t; e<64*128; e+=256){
            int pt = e>>7, j = e&127;
            float v = 0.f;
            if(pt < npts){
                int gi = b*NP + pt0 + pt;
                v = (j < 64) ? g_net[gi*HID + j]
                             : g_binsum[(b*R2 + g_idx[gi])*HID + (j-64)];
            }
            x_s[pt*132+j] = v;
        }
    }
    for(int e=t; e<64*128; e+=256){ int o=e>>7, k=e&127; wA [k*68+o] = W0[e]; }
    for(int e=t; e<64*64;  e+=256){ int o=e>>6, k=e&63;  w1t[k*68+o] = W1[e]; }
    __syncthreads();

    int o0 = (t & 15)*4;
    int pbase = (t >> 4)*4;

    float acc[4][4];
    #pragma unroll
    for(int i=0;i<4;i++){ acc[i][0]=acc[i][1]=acc[i][2]=acc[i][3]=0.f; }
    #pragma unroll 4
    for(int k=0;k<128;k++){
        float4 w = *(const float4*)&wA[k*68 + o0];
        #pragma unroll
        for(int i=0;i<4;i++){
            float xv = x_s[(pbase+i)*132 + k];
            acc[i][0]+=w.x*xv; acc[i][1]+=w.y*xv; acc[i][2]+=w.z*xv; acc[i][3]+=w.w*xv;
        }
    }
    {
        float c0=b0[o0],c1=b0[o0+1],c2=b0[o0+2],c3=b0[o0+3];
        #pragma unroll
        for(int i=0;i<4;i++){
            float4 hv;
            hv.x=fmaxf(acc[i][0]+c0,0.f); hv.y=fmaxf(acc[i][1]+c1,0.f);
            hv.z=fmaxf(acc[i][2]+c2,0.f); hv.w=fmaxf(acc[i][3]+c3,0.f);
            *(float4*)&h_s[(pbase+i)*68 + o0] = hv;
        }
    }
    __syncthreads();
    for(int e=t; e<64*128; e+=256){ int o=e>>7, k=e&127; wA[k*68+o] = Ws[e]; }

    float acd[4][4];
    #pragma unroll
    for(int i=0;i<4;i++){ acd[i][0]=acd[i][1]=acd[i][2]=acd[i][3]=0.f; }
    #pragma unroll 4
    for(int k=0;k<64;k++){
        float4 w = *(const float4*)&w1t[k*68 + o0];
        #pragma unroll
        for(int i=0;i<4;i++){
            float hv = h_s[(pbase+i)*68 + k];
            acd[i][0]+=w.x*hv; acd[i][1]+=w.y*hv; acd[i][2]+=w.z*hv; acd[i][3]+=w.w*hv;
        }
    }
    {
        float c0=b1[o0],c1=b1[o0+1],c2=b1[o0+2],c3=b1[o0+3];
        #pragma unroll
        for(int i=0;i<4;i++){
            acd[i][0]=fmaxf(acd[i][0]+c0,0.f); acd[i][1]=fmaxf(acd[i][1]+c1,0.f);
            acd[i][2]=fmaxf(acd[i][2]+c2,0.f); acd[i][3]=fmaxf(acd[i][3]+c3,0.f);
        }
    }
    __syncthreads();
    #pragma unroll 4
    for(int k=0;k<128;k++){
        float4 w = *(const float4*)&wA[k*68 + o0];
        #pragma unroll
        for(int i=0;i<4;i++){
            float xv = x_s[(pbase+i)*132 + k];
            acd[i][0]+=w.x*xv; acd[i][1]+=w.y*xv; acd[i][2]+=w.z*xv; acd[i][3]+=w.w*xv;
        }
    }
    #pragma unroll
    for(int i=0;i<4;i++){
        int pt = pbase+i;
        if(pt < npts){
            float4 ov = make_float4(acd[i][0],acd[i][1],acd[i][2],acd[i][3]);
            *(float4*)&g_net[(b*NP + pt0 + pt)*HID + o0] = ov;
        }
    }
}

// ---------------- pooling scatter / normalize ----------------
__global__ void k_scatter_net(){
    int i = blockIdx.x*256 + threadIdx.x;
    if(i >= BN*HID) return;
    int ch = i & 63, pt = i >> 6;
    int b = pt / NP;
    int bin = g_idx[pt];
    atomicAdd(&g_binsum[(b*R2 + bin)*HID + ch], g_net[i]);
    if(ch == 0) atomicAdd(&g_bincnt[b*R2 + bin], 1.0f);
}

__global__ void k_poolnorm(){
    int i = blockIdx.x*256 + threadIdx.x;
    if(i >= BATCH*R2*HID) return;
    g_binsum[i] /= fmaxf(g_bincnt[i>>6], 1.0f);
}

// ---------------- fc_c: [64] -> [256] ----------------
#define SM_FCC ((64*68 + 64*260)*4)
__global__ void k_fc_c(const float* __restrict__ Wc, const float* __restrict__ bc){
    extern __shared__ float sm[];
    float* x_s = sm;             // [64][68]
    float* wct = sm + 64*68;     // [64][260]
    int t = threadIdx.x;
    int b = blockIdx.x / NT, tile = blockIdx.x % NT;
    int pt0 = tile*64, npts = min(64, NP - pt0);
    for(int e=t; e<64*64; e+=256){
        int pt = e>>6, k = e&63;
        x_s[pt*68+k] = (pt < npts) ? g_net[(b*NP+pt0+pt)*HID + k] : 0.f;
    }
    for(int e=t; e<256*64; e+=256){
        int o = e>>6, k = e&63;
        wct[k*260 + o] = Wc[e];
    }
    __syncthreads();
    int og = t & 15, pbase = (t>>4)*4;
    for(int oc=0; oc<4; oc++){
        int o0 = oc*64 + og*4;
        float acc[4][4];
        #pragma unroll
        for(int i=0;i<4;i++){ acc[i][0]=acc[i][1]=acc[i][2]=acc[i][3]=0.f; }
        #pragma unroll 4
        for(int k=0;k<64;k++){
            float4 w = *(const float4*)&wct[k*260 + o0];
            #pragma unroll
            for(int i=0;i<4;i++){
                float xv = x_s[(pbase+i)*68 + k];
                acc[i][0]+=w.x*xv; acc[i][1]+=w.y*xv; acc[i][2]+=w.z*xv; acc[i][3]+=w.w*xv;
            }
        }
        float c0=bc[o0],c1=bc[o0+1],c2=bc[o0+2],c3=bc[o0+3];
        #pragma unroll
        for(int i=0;i<4;i++){
            int pt = pbase+i;
            if(pt < npts){
                float4 ov = make_float4(acc[i][0]+c0, acc[i][1]+c1, acc[i][2]+c2, acc[i][3]+c3);
                *(float4*)&g_c[(b*NP+pt0+pt)*FD + o0] = ov;
            }
        }
    }
}

// ---------------- scatter c to 3 planes + normalize ----------------
__global__ void k_scatter_c(){
    int i = blockIdx.x*256 + threadIdx.x;
    if(i >= 3*BN*FD) return;
    int ch = i & 255, r = i >> 8;
    int pl = r / BN, pt = r - pl*BN;
    int b = pt / NP;
    int bin = g_idx[pl*BN + pt];
    atomicAdd(&g_fea[((pl*BATCH+b)*R2 + bin)*FD + ch], g_c[pt*FD + ch]);
    if(ch == 0) atomicAdd(&g_cnt3[(pl*BATCH+b)*R2 + bin], 1.0f);
}

__global__ void k_cnorm(){
    int i = blockIdx.x*256 + threadIdx.x;
    if(i >= 3*BATCH*R2*FD) return;
    g_fea[i] /= fmaxf(g_cnt3[i>>8], 1.0f);
}

// ---------------- conv weight prep: W[oc][ic][3][3] -> g_wt[conv][ch][kk][oc][icp], tf32 ----------------
__global__ void k_wtrans(const float* __restrict__ Wa, const float* __restrict__ Wb){
    int i = blockIdx.x*256 + threadIdx.x;
    if(i >= 2*2304*FD) return;
    int cI = i / (2304*FD);
    int rem = i - cI*(2304*FD);
    int j  = rem & 7;
    int r2 = rem >> 3;
    int oc = r2 & 255;
    int r3 = r2 >> 8;          // ch*9 + kk
    int kk = r3 % 9, ch = r3 / 9;
    const int perm[8] = {0,4,1,5,2,6,3,7};
    int ic = ch*8 + perm[j];
    const float* W = cI ? Wb : Wa;
    float v = W[oc*2304 + ic*9 + kk];
    unsigned u; asm("cvt.rna.tf32.f32 %0, %1;" : "=r"(u) : "f"(v));
    g_wt[i] = __uint_as_float(u);
}

// ---------------- 3x3 conv 256->256 (+bias, relu), TF32 mma.sync implicit GEMM ----------------
#define SM_CONV ((2112 + 9216)*4)

__device__ __forceinline__ float totf(float x){
    unsigned u; asm("cvt.rna.tf32.f32 %0, %1;" : "=r"(u) : "f"(x));
    return __uint_as_float(u);
}

__device__ __forceinline__ void mma8(float* d, uint2 ar0, uint2 ar1, uint2 b){
    // a0=A[q][c]=ar0.x  a1=A[q+8][c]=ar1.x  a2=A[q][c+4]=ar0.y  a3=A[q+8][c+4]=ar1.y
    asm volatile("mma.sync.aligned.m16n8k8.row.col.f32.tf32.tf32.f32 "
        "{%0,%1,%2,%3}, {%4,%5,%6,%7}, {%8,%9}, {%0,%1,%2,%3};"
        : "+f"(d[0]),"+f"(d[1]),"+f"(d[2]),"+f"(d[3])
        : "r"(ar0.x),"r"(ar1.x),"r"(ar0.y),"r"(ar1.y), "r"(b.x),"r"(b.y));
}

__global__ void __launch_bounds__(256) k_conv(
        const float* __restrict__ in, float* __restrict__ out,
        const float* __restrict__ wt, const float* __restrict__ bias)
{
    extern __shared__ float sm[];
    float* in_s = sm;          // [264 pos][8 icp]  (pos = row*66+col; row=y-y0+1, col=x+1)
    float* w_s  = sm + 2112;   // [9 kk][128 oc][8 icp]
    int t = threadIdx.x;
    int lane = t & 31, w = t >> 5;
    int wm = w & 3, wn = w >> 2;          // warp M 0..3, N 0..1
    int q = lane >> 2, c = lane & 3;

    int ocb = blockIdx.x & 1;
    int r = blockIdx.x >> 1;
    int rp = r & 31;
    int pb = r >> 5;                      // plane*BATCH+b, 0..11
    const float* inp  = in  + pb*R2*FD;
    float*       outp = out + pb*R2*FD;
    int y0 = rp*2;
    int px_base = wm*32;

    float acc[2][8][4];
    #pragma unroll
    for(int mt=0; mt<2; mt++)
        #pragma unroll
        for(int nt=0; nt<8; nt++){
            acc[mt][nt][0]=0.f; acc[mt][nt][1]=0.f; acc[mt][nt][2]=0.f; acc[mt][nt][3]=0.f;
        }

    for(int ch=0; ch<32; ch++){
        __syncthreads();
        // stage input halo (4 rows x 66 cols x 8 ic), permuted pairs, tf32
        for(int e=t; e<528; e+=256){
            int pos = e>>1, half = e&1;
            int rr = pos/66, cc = pos - rr*66;
            int yy = y0 + rr - 1, xx = cc - 1;
            float4 v = make_float4(0.f,0.f,0.f,0.f);
            if(yy >= 0 && yy < 64 && (unsigned)xx < 64u)
                v = *(const float4*)&inp[(yy*64+xx)*FD + ch*8 + half*4];
            float* d = &in_s[pos*8 + half];
            d[0]=totf(v.x); d[2]=totf(v.y); d[4]=totf(v.z); d[6]=totf(v.w);
        }
        // stage weights: straight float4 copy (already tf32 + permuted)
        const float* wsrc = &wt[(size_t)(ch*9)*256*8 + ocb*128*8];
        for(int e=t; e<2304; e+=256){
            int kk = e >> 8, rem = e & 255;
            *(float4*)&w_s[kk*1024 + rem*4] =
                *(const float4*)&wsrc[kk*2048 + rem*4];
        }
        __syncthreads();
        #pragma unroll
        for(int kk=0; kk<9; kk++){
            int ky = kk/3, kx = kk - ky*3;
            uint2 a[2][2];
            #pragma unroll
            for(int mt=0; mt<2; mt++){
                int px0 = px_base + mt*16 + q;
                a[mt][0] = *(const uint2*)&in_s[(((px0>>6)+ky)*66 + (px0&63)+kx)*8 + 2*c];
                int px1 = px0 + 8;
                a[mt][1] = *(const uint2*)&in_s[(((px1>>6)+ky)*66 + (px1&63)+kx)*8 + 2*c];
            }
            const float* wb = &w_s[kk*1024 + (wn*64 + q)*8 + 2*c];
            #pragma unroll
            for(int nt=0; nt<8; nt++){
                uint2 b = *(const uint2*)&wb[nt*64];
                mma8(acc[0][nt], a[0][0], a[0][1], b);
                mma8(acc[1][nt], a[1][0], a[1][1], b);
            }
        }
    }
    // epilogue: bias + relu, float2 stores
    int o_base = ocb*128 + wn*64;
    #pragma unroll
    for(int nt=0; nt<8; nt++){
        int oc = o_base + nt*8 + 2*c;
        float2 bb = *(const float2*)&bias[oc];
        #pragma unroll
        for(int mt=0; mt<2; mt++){
            int px0 = px_base + mt*16 + q;
            int y = y0 + (px0>>6), x = px0&63;
            float2 o1;
            o1.x = fmaxf(acc[mt][nt][0]+bb.x, 0.f);
            o1.y = fmaxf(acc[mt][nt][1]+bb.y, 0.f);
            *(float2*)&outp[(y*64+x)*FD + oc] = o1;
            int px1 = px0 + 8;
            y = y0 + (px1>>6); x = px1&63;
            float2 o2;
            o2.x = fmaxf(acc[mt][nt][2]+bb.x, 0.f);
            o2.y = fmaxf(acc[mt][nt][3]+bb.y, 0.f);
            *(float2*)&outp[(y*64+x)*FD + oc] = o2;
        }
    }
}

// ---------------- bilinear grid sample over 3 planes, accumulate ----------------
__global__ void k_sample(const float* __restrict__ query, float* __restrict__ out){
    int gid = blockIdx.x*256 + threadIdx.x;
    int w = gid >> 5, lane = gid & 31;
    if(w >= BN) return;
    int b = w / NP;
    float q0 = query[w*3+0], q1 = query[w*3+1], q2 = query[w*3+2];
    float a0[4] = {0,0,0,0}, a1[4] = {0,0,0,0};
    #pragma unroll
    for(int pl=0; pl<3; pl++){
        float qa = (pl==2) ? q1 : q0;       // coord0 -> W
        float qb = (pl==1) ? q1 : q2;       // coord1 -> H
        float gx = qa*2.0f - 1.0f, gy = qb*2.0f - 1.0f;
        float x = ((gx + 1.0f)*64.0f - 1.0f)*0.5f;
        float y = ((gy + 1.0f)*64.0f - 1.0f)*0.5f;
        x = fminf(fmaxf(x, 0.0f), 63.0f);
        y = fminf(fmaxf(y, 0.0f), 63.0f);
        float x0f = floorf(x), y0f = floorf(y);
        int x0 = (int)x0f, y0 = (int)y0f;
        int x1 = min(x0+1, 63), y1 = min(y0+1, 63);
        float wx = x - x0f, wy = y - y0f;
        const float* f = &g_fea[(pl*BATCH + b)*R2*FD];
        float ww[4] = {(1.f-wx)*(1.f-wy), wx*(1.f-wy), (1.f-wx)*wy, wx*wy};
        int pix[4] = {y0*64+x0, y0*64+x1, y1*64+x0, y1*64+x1};
        #pragma unroll
        for(int tp=0; tp<4; tp++){
            const float* base = f + pix[tp]*FD;
            float4 v0 = *(const float4*)&base[lane*4];
            float4 v1 = *(const float4*)&base[128 + lane*4];
            float g = ww[tp];
            a0[0]+=g*v0.x; a0[1]+=g*v0.y; a0[2]+=g*v0.z; a0[3]+=g*v0.w;
            a1[0]+=g*v1.x; a1[1]+=g*v1.y; a1[2]+=g*v1.z; a1[3]+=g*v1.w;
        }
    }
    float* ob = &out[w*FD];
    *(float4*)&ob[lane*4]       = make_float4(a0[0],a0[1],a0[2],a0[3]);
    *(float4*)&ob[128+lane*4]   = make_float4(a1[0],a1[1],a1[2],a1[3]);
}

// ---------------- launch ----------------
extern "C" void kernel_launch(void* const* d_in, const int* in_sizes, int n_in,
                              void* d_out, int out_size)
{
    const float* p    = (const float*)d_in[0];
    const float* qry  = (const float*)d_in[1];
    const float* fcW  = (const float*)d_in[2];
    const float* fcb  = (const float*)d_in[3];
    const float* W0   = (const float*)d_in[4];
    const float* b0   = (const float*)d_in[5];
    const float* W1   = (const float*)d_in[6];
    const float* b1   = (const float*)d_in[7];
    const float* Ws   = (const float*)d_in[8];
    const float* Wc   = (const float*)d_in[9];
    const float* bc   = (const float*)d_in[10];
    const float* C1W  = (const float*)d_in[11];
    const float* C1b  = (const float*)d_in[12];
    const float* C2W  = (const float*)d_in[13];
    const float* C2b  = (const float*)d_in[14];
    float* out = (float*)d_out;

    cudaFuncSetAttribute(k_block, cudaFuncAttributeMaxDynamicSharedMemorySize, SM_BLOCK);
    cudaFuncSetAttribute(k_fc_c,  cudaFuncAttributeMaxDynamicSharedMemorySize, SM_FCC);
    cudaFuncSetAttribute(k_conv,  cudaFuncAttributeMaxDynamicSharedMemorySize, SM_CONV);

    void *binsum_p, *bincnt_p, *fea_p, *cnt3_p, *feb_p, *wt_p;
    cudaGetSymbolAddress(&binsum_p, g_binsum);
    cudaGetSymbolAddress(&bincnt_p, g_bincnt);
    cudaGetSymbolAddress(&fea_p,    g_fea);
    cudaGetSymbolAddress(&feb_p,    g_feb);
    cudaGetSymbolAddress(&cnt3_p,   g_cnt3);
    cudaGetSymbolAddress(&wt_p,     g_wt);

    k_idx<<<(BN+255)/256, 256>>>(p);
    k_block<<<BATCH*NT, 256, SM_BLOCK>>>(0, p, fcW, fcb, W0, b0, W1, b1, Ws);

    for(int it=1; it<=2; it++){
        cudaMemsetAsync(binsum_p, 0, (size_t)BATCH*R2*HID*4);
        cudaMemsetAsync(bincnt_p, 0, (size_t)BATCH*R2*4);
        k_scatter_net<<<(BN*HID+255)/256, 256>>>();
        k_poolnorm<<<(BATCH*R2*HID+255)/256, 256>>>();
        k_block<<<BATCH*NT, 256, SM_BLOCK>>>(it, p, fcW, fcb,
                 W0 + it*HID*128, b0 + it*HID, W1 + it*HID*HID, b1 + it*HID, Ws + it*HID*128);
    }

    k_fc_c<<<BATCH*NT, 256, SM_FCC>>>(Wc, bc);

    cudaMemsetAsync(fea_p,  0, (size_t)3*BATCH*R2*FD*4);
    cudaMemsetAsync(cnt3_p, 0, (size_t)3*BATCH*R2*4);
    k_scatter_c<<<(3*BN*FD)/256, 256>>>();
    k_cnorm<<<(3*BATCH*R2*FD)/256, 256>>>();

    k_wtrans<<<(2*2304*FD)/256, 256>>>(C1W, C2W);

    k_conv<<<12*32*2, 256, SM_CONV>>>((const float*)fea_p, (float*)feb_p,
                                      (const float*)wt_p,               C1b);
    k_conv<<<12*32*2, 256, SM_CONV>>>((const float*)feb_p, (float*)fea_p,
                                      (const float*)wt_p + 2304*FD,     C2b);

    k_sample<<<(BN*32)/256, 256>>>(qry, out);
}

// round 4
// speedup vs baseline: 2.6329x; 1.2207x over previous
#include <cuda_runtime.h>

#define BATCH 4
#define NP 30000
#define BN (BATCH*NP)
#define HID 64
#define FD 256
#define R2 4096
#define NT 469   /* ceil(NP/64) */
#define NBROW (3*BATCH*R2)   /* 49152 plane-batch-bin rows */

// ---------------- scratch (no allocation allowed) ----------------
__device__ float g_net[BN*HID];                      // 30.7 MB
__device__ int   g_idx[3*BN];
__device__ float g_binsum[BATCH*R2*HID];             // pooling scratch
__device__ float g_bincnt[BATCH*R2];
__device__ float g_nsum[NBROW*HID];                  // 12.6 MB final-net bin sums
__device__ float g_cnt3[NBROW];
__device__ __align__(128) float g_fea[NBROW*FD];     // conv1 in  (permuted tf32)
__device__ __align__(128) float g_feb[NBROW*FD];     // conv1 out (permuted tf32)
__device__ __align__(128) float g_fec[NBROW*FD];     // conv2 out (natural fp32)
__device__ __align__(128) float g_wt[2*2304*FD];     // tf32 wt [conv][ch][kk][oc][icp]

// ---------------- helpers ----------------
__device__ __forceinline__ float totf(float x){
    unsigned u; asm("cvt.rna.tf32.f32 %0, %1;" : "=r"(u) : "f"(x));
    return __uint_as_float(u);
}
__device__ __forceinline__ void cpa(unsigned d, const void* s, int sz){
    asm volatile("cp.async.cg.shared.global [%0], [%1], 16, %2;" :: "r"(d), "l"(s), "r"(sz));
}
#define CP_COMMIT asm volatile("cp.async.commit_group;")
#define CP_WAIT0  asm volatile("cp.async.wait_group 0;")

// ---------------- bin indices ----------------
__device__ __forceinline__ int binof(float v){
    const float DEN = (float)(1.0 + 0.1 + 1e-6);
    float w = (v + 0.5f) / DEN;
    w = fminf(fmaxf(w, 0.0f), (float)(1.0 - 1e-6));
    return (int)(w * 64.0f);
}

__global__ void k_idx(const float* __restrict__ p){
    int i = blockIdx.x*256 + threadIdx.x;
    if(i >= BN) return;
    float x = p[i*3+0], y = p[i*3+1], z = p[i*3+2];
    int bx = binof(x), by = binof(y), bz = binof(z);
    g_idx[0*BN+i] = bx + 64*bz;
    g_idx[1*BN+i] = bx + 64*by;
    g_idx[2*BN+i] = by + 64*bz;
}

// ---------------- fused resblock ----------------
#define SM_BLOCK ((64*132 + 64*68 + 128*68 + 64*68)*4)

__global__ void k_block(int mode, const float* __restrict__ p,
                        const float* __restrict__ fcW, const float* __restrict__ fcb,
                        const float* __restrict__ W0, const float* __restrict__ b0,
                        const float* __restrict__ W1, const float* __restrict__ b1,
                        const float* __restrict__ Ws)
{
    extern __shared__ float sm[];
    float* x_s = sm;                  // [64][132]
    float* h_s = x_s + 64*132;        // [64][68]
    float* wA  = h_s + 64*68;         // [128][68]
    float* w1t = wA  + 128*68;        // [64][68]
    int t = threadIdx.x;
    int b = blockIdx.x / NT, tile = blockIdx.x % NT;
    int pt0 = tile*64;
    int npts = min(64, NP - pt0);

    if(mode == 0){
        for(int e=t; e<64*128; e+=256){
            int pt = e>>7, j = e&127;
            float v = 0.f;
            if(pt < npts){
                int gp = (b*NP + pt0 + pt)*3;
                v = fcb[j] + p[gp]*fcW[j*3] + p[gp+1]*fcW[j*3+1] + p[gp+2]*fcW[j*3+2];
            }
            x_s[pt*132+j] = v;
        }
    } else {
        for(int e=t; e<64*128; e+=256){
            int pt = e>>7, j = e&127;
            float v = 0.f;
            if(pt < npts){
                int gi = b*NP + pt0 + pt;
                v = (j < 64) ? g_net[gi*HID + j]
                             : g_binsum[(b*R2 + g_idx[gi])*HID + (j-64)];
            }
            x_s[pt*132+j] = v;
        }
    }
    for(int e=t; e<64*128; e+=256){ int o=e>>7, k=e&127; wA [k*68+o] = W0[e]; }
    for(int e=t; e<64*64;  e+=256){ int o=e>>6, k=e&63;  w1t[k*68+o] = W1[e]; }
    __syncthreads();

    int o0 = (t & 15)*4;
    int pbase = (t >> 4)*4;

    float acc[4][4];
    #pragma unroll
    for(int i=0;i<4;i++){ acc[i][0]=acc[i][1]=acc[i][2]=acc[i][3]=0.f; }
    #pragma unroll 4
    for(int k=0;k<128;k++){
        float4 w = *(const float4*)&wA[k*68 + o0];
        #pragma unroll
        for(int i=0;i<4;i++){
            float xv = x_s[(pbase+i)*132 + k];
            acc[i][0]+=w.x*xv; acc[i][1]+=w.y*xv; acc[i][2]+=w.z*xv; acc[i][3]+=w.w*xv;
        }
    }
    {
        float c0=b0[o0],c1=b0[o0+1],c2=b0[o0+2],c3=b0[o0+3];
        #pragma unroll
        for(int i=0;i<4;i++){
            float4 hv;
            hv.x=fmaxf(acc[i][0]+c0,0.f); hv.y=fmaxf(acc[i][1]+c1,0.f);
            hv.z=fmaxf(acc[i][2]+c2,0.f); hv.w=fmaxf(acc[i][3]+c3,0.f);
            *(float4*)&h_s[(pbase+i)*68 + o0] = hv;
        }
    }
    __syncthreads();
    for(int e=t; e<64*128; e+=256){ int o=e>>7, k=e&127; wA[k*68+o] = Ws[e]; }

    float acd[4][4];
    #pragma unroll
    for(int i=0;i<4;i++){ acd[i][0]=acd[i][1]=acd[i][2]=acd[i][3]=0.f; }
    #pragma unroll 4
    for(int k=0;k<64;k++){
        float4 w = *(const float4*)&w1t[k*68 + o0];
        #pragma unroll
        for(int i=0;i<4;i++){
            float hv = h_s[(pbase+i)*68 + k];
            acd[i][0]+=w.x*hv; acd[i][1]+=w.y*hv; acd[i][2]+=w.z*hv; acd[i][3]+=w.w*hv;
        }
    }
    {
        float c0=b1[o0],c1=b1[o0+1],c2=b1[o0+2],c3=b1[o0+3];
        #pragma unroll
        for(int i=0;i<4;i++){
            acd[i][0]=fmaxf(acd[i][0]+c0,0.f); acd[i][1]=fmaxf(acd[i][1]+c1,0.f);
            acd[i][2]=fmaxf(acd[i][2]+c2,0.f); acd[i][3]=fmaxf(acd[i][3]+c3,0.f);
        }
    }
    __syncthreads();
    #pragma unroll 4
    for(int k=0;k<128;k++){
        float4 w = *(const float4*)&wA[k*68 + o0];
        #pragma unroll
        for(int i=0;i<4;i++){
            float xv = x_s[(pbase+i)*132 + k];
            acd[i][0]+=w.x*xv; acd[i][1]+=w.y*xv; acd[i][2]+=w.z*xv; acd[i][3]+=w.w*xv;
        }
    }
    #pragma unroll
    for(int i=0;i<4;i++){
        int pt = pbase+i;
        if(pt < npts){
            float4 ov = make_float4(acd[i][0],acd[i][1],acd[i][2],acd[i][3]);
            *(float4*)&g_net[(b*NP + pt0 + pt)*HID + o0] = ov;
        }
    }
}

// ---------------- pooling scatter / normalize (xz plane, loop iterations) ----------------
__global__ void k_scatter_net(){
    int i = blockIdx.x*256 + threadIdx.x;
    if(i >= BN*HID) return;
    int ch = i & 63, pt = i >> 6;
    int b = pt / NP;
    int bin = g_idx[pt];
    atomicAdd(&g_binsum[(b*R2 + bin)*HID + ch], g_net[i]);
    if(ch == 0) atomicAdd(&g_bincnt[b*R2 + bin], 1.0f);
}

__global__ void k_poolnorm(){
    int i = blockIdx.x*256 + threadIdx.x;
    if(i >= BATCH*R2*HID) return;
    g_binsum[i] /= fmaxf(g_bincnt[i>>6], 1.0f);
}

// ---------------- final-net scatter to 3 planes ----------------
__global__ void k_scatter_net3(){
    int i = blockIdx.x*256 + threadIdx.x;
    if(i >= 3*BN*HID) return;
    int ch = i & 63, r = i >> 6;      // r = pl*BN + pt
    int pl = r / BN, pt = r - pl*BN;
    int b = pt / NP;
    int row = (pl*BATCH + b)*R2 + g_idx[pl*BN + pt];
    atomicAdd(&g_nsum[row*HID + ch], g_net[pt*HID + ch]);
    if(ch == 0) atomicAdd(&g_cnt3[row], 1.0f);
}

// ---------------- bin GEMM: fea = gate(cnt) * ((nsum/max(cnt,1)) @ Wc^T + bc), permuted tf32 ----------------
#define SM_FCC ((64*68 + 64*260)*4)
__global__ void k_fcc_bins(const float* __restrict__ Wc, const float* __restrict__ bc){
    extern __shared__ float sm[];
    float* x_s = sm;             // [64][68]
    float* wct = sm + 64*68;     // [64][260]
    int t = threadIdx.x;
    int r0 = blockIdx.x*64;      // 768 blocks x 64 rows
    for(int e=t; e<64*64; e+=256){
        int pt = e>>6, k = e&63;
        int row = r0 + pt;
        float cnt = g_cnt3[row];
        x_s[pt*68+k] = g_nsum[row*HID + k] / fmaxf(cnt, 1.0f);
    }
    for(int e=t; e<256*64; e+=256){
        int o = e>>6, k = e&63;
        wct[k*260 + o] = Wc[e];
    }
    __syncthreads();
    const int iperm[8] = {0,2,4,6,1,3,5,7};
    int og = t & 15, pbase = (t>>4)*4;
    for(int oc4=0; oc4<4; oc4++){
        int o0 = oc4*64 + og*4;
        float acc[4][4];
        #pragma unroll
        for(int i=0;i<4;i++){ acc[i][0]=acc[i][1]=acc[i][2]=acc[i][3]=0.f; }
        #pragma unroll 4
        for(int k=0;k<64;k++){
            float4 w = *(const float4*)&wct[k*260 + o0];
            #pragma unroll
            for(int i=0;i<4;i++){
                float xv = x_s[(pbase+i)*68 + k];
                acc[i][0]+=w.x*xv; acc[i][1]+=w.y*xv; acc[i][2]+=w.z*xv; acc[i][3]+=w.w*xv;
            }
        }
        float c0=bc[o0],c1=bc[o0+1],c2=bc[o0+2],c3=bc[o0+3];
        int jb = o0 & 7;   // 0 or 4
        #pragma unroll
        for(int i=0;i<4;i++){
            int row = r0 + pbase + i;
            float gate = (g_cnt3[row] > 0.f) ? 1.f : 0.f;
            float* d = &g_fea[row*FD + (o0 & ~7)];
            d[iperm[jb+0]] = totf(gate*(acc[i][0]+c0));
            d[iperm[jb+1]] = totf(gate*(acc[i][1]+c1));
            d[iperm[jb+2]] = totf(gate*(acc[i][2]+c2));
            d[iperm[jb+3]] = totf(gate*(acc[i][3]+c3));
        }
    }
}

// ---------------- conv weight prep: tf32 + fragment permuted ----------------
__global__ void k_wtrans(const float* __restrict__ Wa, const float* __restrict__ Wb){
    int i = blockIdx.x*256 + threadIdx.x;
    if(i >= 2*2304*FD) return;
    int cI = i / (2304*FD);
    int rem = i - cI*(2304*FD);
    int j  = rem & 7;
    int r2 = rem >> 3;
    int oc = r2 & 255;
    int r3 = r2 >> 8;          // ch*9 + kk
    int kk = r3 % 9, ch = r3 / 9;
    const int perm[8] = {0,4,1,5,2,6,3,7};
    int ic = ch*8 + perm[j];
    const float* W = cI ? Wb : Wa;
    g_wt[i] = totf(W[oc*2304 + ic*9 + kk]);
}

// ---------------- 3x3 conv 256->256 (+bias, relu), TF32 mma, cp.async double-buffered ----------------
#define SM_CONV ((2*2112 + 2*9216)*4)

__device__ __forceinline__ void mma8(float* d, uint2 ar0, uint2 ar1, uint2 b){
    asm volatile("mma.sync.aligned.m16n8k8.row.col.f32.tf32.tf32.f32 "
        "{%0,%1,%2,%3}, {%4,%5,%6,%7}, {%8,%9}, {%0,%1,%2,%3};"
        : "+f"(d[0]),"+f"(d[1]),"+f"(d[2]),"+f"(d[3])
        : "r"(ar0.x),"r"(ar1.x),"r"(ar0.y),"r"(ar1.y), "r"(b.x),"r"(b.y));
}

__global__ void __launch_bounds__(256) k_conv(
        const float* __restrict__ in, float* __restrict__ out,
        const float* __restrict__ wt, const float* __restrict__ bias, int permout)
{
    extern __shared__ float sm[];
    float* ibuf = sm;              // [2][264*8]
    float* wbuf = sm + 2*2112;     // [2][9*128*8]
    unsigned ib_u = (unsigned)__cvta_generic_to_shared(ibuf);
    unsigned wb_u = (unsigned)__cvta_generic_to_shared(wbuf);
    int t = threadIdx.x;
    int lane = t & 31, w = t >> 5;
    int wm = w & 3, wn = w >> 2;
    int q = lane >> 2, c = lane & 3;

    int ocb = blockIdx.x & 1;
    int r = blockIdx.x >> 1;
    int rp = r & 31;
    int pb = r >> 5;
    const float* inp  = in  + pb*R2*FD;
    float*       outp = out + pb*R2*FD;
    int y0 = rp*2;
    int px_base = wm*32;

    float acc[2][8][4];
    #pragma unroll
    for(int mt=0; mt<2; mt++)
        #pragma unroll
        for(int nt=0; nt<8; nt++){
            acc[mt][nt][0]=0.f; acc[mt][nt][1]=0.f; acc[mt][nt][2]=0.f; acc[mt][nt][3]=0.f;
        }

    // stage chunk ch into buffer buf (all cp.async, 16B granules)
    auto stage = [&](int ch, int buf){
        for(int e=t; e<528; e+=256){
            int pos = e>>1, half = e&1;
            int rr = pos/66, cc = pos - rr*66;
            int yy = y0 + rr - 1, xx = cc - 1;
            bool ok = (yy >= 0 && yy < 64 && (unsigned)xx < 64u);
            const float* src = inp + ((ok ? (yy*64+xx) : 0)*FD + ch*8 + half*4);
            cpa(ib_u + (unsigned)(buf*2112*4 + pos*32 + half*16), src, ok ? 16 : 0);
        }
        const float* wsrc = wt + (size_t)ch*18432 + ocb*1024;
        for(int e=t; e<2304; e+=256){
            int kk = e>>8, rem = e&255;
            cpa(wb_u + (unsigned)(buf*9216*4 + kk*4096 + rem*16),
                wsrc + kk*2048 + rem*4, 16);
        }
        CP_COMMIT;
    };

    stage(0, 0);
    for(int ch=0; ch<32; ch++){
        int cur = ch & 1;
        CP_WAIT0;
        __syncthreads();
        if(ch < 31) stage(ch+1, 1-cur);
        const float* in_s = ibuf + cur*2112;
        const float* w_s  = wbuf + cur*9216;
        #pragma unroll
        for(int kk=0; kk<9; kk++){
            int ky = kk/3, kx = kk - ky*3;
            uint2 a[2][2];
            #pragma unroll
            for(int mt=0; mt<2; mt++){
                int px0 = px_base + mt*16 + q;
                a[mt][0] = *(const uint2*)&in_s[(((px0>>6)+ky)*66 + (px0&63)+kx)*8 + 2*c];
                int px1 = px0 + 8;
                a[mt][1] = *(const uint2*)&in_s[(((px1>>6)+ky)*66 + (px1&63)+kx)*8 + 2*c];
            }
            const float* wb = &w_s[kk*1024 + (wn*64 + q)*8 + 2*c];
            #pragma unroll
            for(int nt=0; nt<8; nt++){
                uint2 b = *(const uint2*)&wb[nt*64];
                mma8(acc[0][nt], a[0][0], a[0][1], b);
                mma8(acc[1][nt], a[1][0], a[1][1], b);
            }
        }
        __syncthreads();
    }

    int o_base = ocb*128 + wn*64;
    const int iperm[8] = {0,2,4,6,1,3,5,7};
    #pragma unroll
    for(int nt=0; nt<8; nt++){
        int oc = o_base + nt*8 + 2*c;
        float2 bb = *(const float2*)&bias[oc];
        #pragma unroll
        for(int mt=0; mt<2; mt++){
            #pragma unroll
            for(int half=0; half<2; half++){
                int px = px_base + mt*16 + q + half*8;
                int y = y0 + (px>>6), x = px&63;
                float v0 = fmaxf(acc[mt][nt][half*2+0]+bb.x, 0.f);
                float v1 = fmaxf(acc[mt][nt][half*2+1]+bb.y, 0.f);
                float* d = &outp[(y*64+x)*FD];
                if(permout){
                    d[(oc & ~7) + iperm[2*c]]   = totf(v0);
                    d[(oc & ~7) + iperm[2*c+1]] = totf(v1);
                } else {
                    *(float2*)&d[oc] = make_float2(v0, v1);
                }
            }
        }
    }
}

// ---------------- bilinear grid sample over 3 planes, accumulate ----------------
__global__ void k_sample(const float* __restrict__ query, float* __restrict__ out){
    int gid = blockIdx.x*256 + threadIdx.x;
    int w = gid >> 5, lane = gid & 31;
    if(w >= BN) return;
    int b = w / NP;
    float q0 = query[w*3+0], q1 = query[w*3+1], q2 = query[w*3+2];
    float a0[4] = {0,0,0,0}, a1[4] = {0,0,0,0};
    #pragma unroll
    for(int pl=0; pl<3; pl++){
        float qa = (pl==2) ? q1 : q0;
        float qb = (pl==1) ? q1 : q2;
        float gx = qa*2.0f - 1.0f, gy = qb*2.0f - 1.0f;
        float x = ((gx + 1.0f)*64.0f - 1.0f)*0.5f;
        float y = ((gy + 1.0f)*64.0f - 1.0f)*0.5f;
        x = fminf(fmaxf(x, 0.0f), 63.0f);
        y = fminf(fmaxf(y, 0.0f), 63.0f);
        float x0f = floorf(x), y0f = floorf(y);
        int x0 = (int)x0f, y0 = (int)y0f;
        int x1 = min(x0+1, 63), y1 = min(y0+1, 63);
        float wx = x - x0f, wy = y - y0f;
        const float* f = &g_fec[(pl*BATCH + b)*R2*FD];
        float ww[4] = {(1.f-wx)*(1.f-wy), wx*(1.f-wy), (1.f-wx)*wy, wx*wy};
        int pix[4] = {y0*64+x0, y0*64+x1, y1*64+x0, y1*64+x1};
        #pragma unroll
        for(int tp=0; tp<4; tp++){
            const float* base = f + pix[tp]*FD;
            float4 v0 = *(const float4*)&base[lane*4];
            float4 v1 = *(const float4*)&base[128 + lane*4];
            float g = ww[tp];
            a0[0]+=g*v0.x; a0[1]+=g*v0.y; a0[2]+=g*v0.z; a0[3]+=g*v0.w;
            a1[0]+=g*v1.x; a1[1]+=g*v1.y; a1[2]+=g*v1.z; a1[3]+=g*v1.w;
        }
    }
    float* ob = &out[w*FD];
    *(float4*)&ob[lane*4]       = make_float4(a0[0],a0[1],a0[2],a0[3]);
    *(float4*)&ob[128+lane*4]   = make_float4(a1[0],a1[1],a1[2],a1[3]);
}

// ---------------- launch ----------------
extern "C" void kernel_launch(void* const* d_in, const int* in_sizes, int n_in,
                              void* d_out, int out_size)
{
    const float* p    = (const float*)d_in[0];
    const float* qry  = (const float*)d_in[1];
    const float* fcW  = (const float*)d_in[2];
    const float* fcb  = (const float*)d_in[3];
    const float* W0   = (const float*)d_in[4];
    const float* b0   = (const float*)d_in[5];
    const float* W1   = (const float*)d_in[6];
    const float* b1   = (const float*)d_in[7];
    const float* Ws   = (const float*)d_in[8];
    const float* Wc   = (const float*)d_in[9];
    const float* bc   = (const float*)d_in[10];
    const float* C1W  = (const float*)d_in[11];
    const float* C1b  = (const float*)d_in[12];
    const float* C2W  = (const float*)d_in[13];
    const float* C2b  = (const float*)d_in[14];
    float* out = (float*)d_out;

    cudaFuncSetAttribute(k_block,    cudaFuncAttributeMaxDynamicSharedMemorySize, SM_BLOCK);
    cudaFuncSetAttribute(k_fcc_bins, cudaFuncAttributeMaxDynamicSharedMemorySize, SM_FCC);
    cudaFuncSetAttribute(k_conv,     cudaFuncAttributeMaxDynamicSharedMemorySize, SM_CONV);

    void *binsum_p, *bincnt_p, *nsum_p, *cnt3_p, *fea_p, *feb_p, *wt_p;
    cudaGetSymbolAddress(&binsum_p, g_binsum);
    cudaGetSymbolAddress(&bincnt_p, g_bincnt);
    cudaGetSymbolAddress(&nsum_p,   g_nsum);
    cudaGetSymbolAddress(&cnt3_p,   g_cnt3);
    cudaGetSymbolAddress(&fea_p,    g_fea);
    cudaGetSymbolAddress(&feb_p,    g_feb);
    cudaGetSymbolAddress(&wt_p,     g_wt);

    k_idx<<<(BN+255)/256, 256>>>(p);
    k_wtrans<<<(2*2304*FD)/256, 256>>>(C1W, C2W);
    k_block<<<BATCH*NT, 256, SM_BLOCK>>>(0, p, fcW, fcb, W0, b0, W1, b1, Ws);

    for(int it=1; it<=2; it++){
        cudaMemsetAsync(binsum_p, 0, (size_t)BATCH*R2*HID*4);
        cudaMemsetAsync(bincnt_p, 0, (size_t)BATCH*R2*4);
        k_scatter_net<<<(BN*HID+255)/256, 256>>>();
        k_poolnorm<<<(BATCH*R2*HID+255)/256, 256>>>();
        k_block<<<BATCH*NT, 256, SM_BLOCK>>>(it, p, fcW, fcb,
                 W0 + it*HID*128, b0 + it*HID, W1 + it*HID*HID, b1 + it*HID, Ws + it*HID*128);
    }

    cudaMemsetAsync(nsum_p, 0, (size_t)NBROW*HID*4);
    cudaMemsetAsync(cnt3_p, 0, (size_t)NBROW*4);
    k_scatter_net3<<<(3*BN*HID+255)/256, 256>>>();
    k_fcc_bins<<<NBROW/64, 256, SM_FCC>>>(Wc, bc);

    k_conv<<<12*32*2, 256, SM_CONV>>>((const float*)fea_p, (float*)feb_p,
                                      (const float*)wt_p,               C1b, 1);
    void* fec_p; cudaGetSymbolAddress(&fec_p, g_fec);
    k_conv<<<12*32*2, 256, SM_CONV>>>((const float*)feb_p, (float*)fec_p,
                                      (const float*)wt_p + 2304*FD,     C2b, 0);

    k_sample<<<(BN*32)/256, 256>>>(qry, out);
}

// round 5
// speedup vs baseline: 3.3112x; 1.2576x over previous
#include <cuda_runtime.h>

#define BATCH 4
#define NP 30000
#define BN (BATCH*NP)
#define HID 64
#define FD 256
#define R2 4096
#define NT 469   /* ceil(NP/64) */
#define NBROW (3*BATCH*R2)   /* 49152 plane-batch-bin rows */

// ---------------- scratch (no allocation allowed) ----------------
__device__ float g_net[BN*HID];
__device__ int   g_idx[3*BN];
__device__ float g_binsum[BATCH*R2*HID];
__device__ float g_bincnt[BATCH*R2];
__device__ float g_nsum[NBROW*HID];
__device__ float g_cnt3[NBROW];
__device__ __align__(128) float g_fea[NBROW*FD];     // conv1 in  (permuted tf32)
__device__ __align__(128) float g_feb[NBROW*FD];     // conv1 out (permuted tf32)
__device__ __align__(128) float g_fec[NBROW*FD];     // conv2 out (natural fp32)
__device__ __align__(128) float g_wt[2*2304*FD];     // conv tf32 wt [conv][ch][kk][oc][icp]
__device__ __align__(128) float g_wblk[3*20480];     // resblock tf32 wt per mode: w0[16][64][8], w1[8][64][8], ws[16][64][8]

// ---------------- helpers ----------------
__device__ __forceinline__ float totf(float x){
    unsigned u; asm("cvt.rna.tf32.f32 %0, %1;" : "=r"(u) : "f"(x));
    return __uint_as_float(u);
}
__device__ __forceinline__ void cpa(unsigned d, const void* s, int sz){
    asm volatile("cp.async.cg.shared.global [%0], [%1], 16, %2;" :: "r"(d), "l"(s), "r"(sz));
}
#define CP_COMMIT asm volatile("cp.async.commit_group;")
#define CP_WAIT0  asm volatile("cp.async.wait_group 0;")

__device__ __forceinline__ void mma8(float* d, uint2 ar0, uint2 ar1, uint2 b){
    asm volatile("mma.sync.aligned.m16n8k8.row.col.f32.tf32.tf32.f32 "
        "{%0,%1,%2,%3}, {%4,%5,%6,%7}, {%8,%9}, {%0,%1,%2,%3};"
        : "+f"(d[0]),"+f"(d[1]),"+f"(d[2]),"+f"(d[3])
        : "r"(ar0.x),"r"(ar1.x),"r"(ar0.y),"r"(ar1.y), "r"(b.x),"r"(b.y));
}

// ---------------- bin indices ----------------
__device__ __forceinline__ int binof(float v){
    const float DEN = (float)(1.0 + 0.1 + 1e-6);
    float w = (v + 0.5f) / DEN;
    w = fminf(fmaxf(w, 0.0f), (float)(1.0 - 1e-6));
    return (int)(w * 64.0f);
}

__global__ void k_idx(const float* __restrict__ p){
    int i = blockIdx.x*256 + threadIdx.x;
    if(i >= BN) return;
    float x = p[i*3+0], y = p[i*3+1], z = p[i*3+2];
    int bx = binof(x), by = binof(y), bz = binof(z);
    g_idx[0*BN+i] = bx + 64*bz;
    g_idx[1*BN+i] = bx + 64*by;
    g_idx[2*BN+i] = by + 64*bz;
}

// ---------------- resblock weight prep: tf32 + fragment permuted ----------------
// layout per mode (20480 floats): [0,8192) W0 [kc][n][8] ; [8192,12288) W1 [kc][n][8] ; [12288,20480) Ws
__global__ void k_wblk(const float* __restrict__ W0, const float* __restrict__ W1,
                       const float* __restrict__ Ws){
    int i = blockIdx.x*256 + threadIdx.x;
    if(i >= 3*20480) return;
    int m = i / 20480, r = i - m*20480;
    const float* src; int kc, n, s, K;
    if(r < 8192){ src = W0 + m*64*128; kc = r>>9; n = (r>>3)&63; s = r&7; K = 128; }
    else if(r < 12288){ int q = r-8192; src = W1 + m*64*64; kc = q>>9; n = (q>>3)&63; s = q&7; K = 64; }
    else { int q = r-12288; src = Ws + m*64*128; kc = q>>9; n = (q>>3)&63; s = q&7; K = 128; }
    int k = kc*8 + (s&1)*4 + (s>>1);
    g_wblk[i] = totf(src[n*K + k]);
}

// ---------------- fused resblock, TF32 mma ----------------
#define SM_BLOCK ((8192 + 4096 + 20480)*4)

__global__ void __launch_bounds__(256) k_block(int mode, const float* __restrict__ p,
                        const float* __restrict__ fcW, const float* __restrict__ fcb,
                        const float* __restrict__ b0g, const float* __restrict__ b1g)
{
    extern __shared__ float sm[];
    float* x_s  = sm;              // [16 kc][64 pt][8 slot]
    float* h_s  = sm + 8192;       // [8 kc][64 pt][8]
    float* wall = sm + 12288;      // 20480: w0 | w1 | ws
    float* w0_s = wall;
    float* w1_s = wall + 8192;
    float* ws_s = wall + 12288;
    unsigned wall_u = (unsigned)__cvta_generic_to_shared(wall);

    int t = threadIdx.x;
    int lane = t & 31, w = t >> 5;
    int wm = w & 3, wn = w >> 2;
    int q = lane >> 2, c = lane & 3;
    int s0 = (c < 2) ? 4*c     : 4*c - 7;   // slot of k=2c
    int s1 = (c < 2) ? 4*c + 2 : 4*c - 5;   // slot of k=2c+1

    int b = blockIdx.x / NT, tile = blockIdx.x % NT;
    int pt0 = tile*64;
    int npts = min(64, NP - pt0);
    int gbase = b*NP + pt0;

    // weights via cp.async (pre-permuted tf32)
    {
        const float* wsrc = g_wblk + mode*20480;
        for(int e=t; e<5120; e+=256)
            cpa(wall_u + (unsigned)e*16, wsrc + e*4, 16);
        CP_COMMIT;
    }

    // stage x tile (tf32, fragment-permuted)
    if(mode == 0){
        for(int e=t; e<2048; e+=256){
            int pt = e>>5, g = e&31;
            int kc = g>>1, half = g&1;
            int kb = kc*8 + half*4;
            float* d = &x_s[kc*512 + pt*8 + half];
            if(pt < npts){
                int gp = (gbase + pt)*3;
                float px = p[gp], py = p[gp+1], pz = p[gp+2];
                #pragma unroll
                for(int i2=0;i2<4;i2++){
                    int j = kb + i2;
                    float v = fcb[j] + px*fcW[j*3] + py*fcW[j*3+1] + pz*fcW[j*3+2];
                    d[2*i2] = totf(v);
                }
            } else {
                d[0]=0.f; d[2]=0.f; d[4]=0.f; d[6]=0.f;
            }
        }
    } else {
        for(int e=t; e<2048; e+=256){
            int pt = e>>5, g = e&31;
            int kc = g>>1, half = g&1;
            float4 v = make_float4(0.f,0.f,0.f,0.f);
            if(pt < npts){
                int gi = gbase + pt;
                if(kc < 8) v = *(const float4*)&g_net[gi*HID + kc*8 + half*4];
                else       v = *(const float4*)&g_binsum[(b*R2 + g_idx[gi])*HID + (kc-8)*8 + half*4];
            }
            float* d = &x_s[kc*512 + pt*8 + half];
            d[0]=totf(v.x); d[2]=totf(v.y); d[4]=totf(v.z); d[6]=totf(v.w);
        }
    }
    CP_WAIT0;
    __syncthreads();

    int row0 = wm*16 + q, row1 = row0 + 8;

    // GEMM1: h = relu(x @ W0^T + b0)
    float aH[4][4];
    #pragma unroll
    for(int nt=0;nt<4;nt++){ aH[nt][0]=aH[nt][1]=aH[nt][2]=aH[nt][3]=0.f; }
    #pragma unroll 4
    for(int kc=0; kc<16; kc++){
        uint2 a0 = *(const uint2*)&x_s[kc*512 + row0*8 + 2*c];
        uint2 a1 = *(const uint2*)&x_s[kc*512 + row1*8 + 2*c];
        #pragma unroll
        for(int nt=0; nt<4; nt++){
            uint2 bb = *(const uint2*)&w0_s[kc*512 + (wn*32 + nt*8 + q)*8 + 2*c];
            mma8(aH[nt], a0, a1, bb);
        }
    }
    #pragma unroll
    for(int nt=0; nt<4; nt++){
        int j0 = wn*32 + nt*8 + 2*c;
        float2 bb = *(const float2*)&b0g[j0];
        int kcd = j0 >> 3;
        float* dl = &h_s[kcd*512];
        dl[row0*8 + s0] = totf(fmaxf(aH[nt][0]+bb.x, 0.f));
        dl[row0*8 + s1] = totf(fmaxf(aH[nt][1]+bb.y, 0.f));
        dl[row1*8 + s0] = totf(fmaxf(aH[nt][2]+bb.x, 0.f));
        dl[row1*8 + s1] = totf(fmaxf(aH[nt][3]+bb.y, 0.f));
    }
    __syncthreads();

    // GEMM2: dx = relu(h @ W1^T + b1)
    float aD[4][4];
    #pragma unroll
    for(int nt=0;nt<4;nt++){ aD[nt][0]=aD[nt][1]=aD[nt][2]=aD[nt][3]=0.f; }
    #pragma unroll 4
    for(int kc=0; kc<8; kc++){
        uint2 a0 = *(const uint2*)&h_s[kc*512 + row0*8 + 2*c];
        uint2 a1 = *(const uint2*)&h_s[kc*512 + row1*8 + 2*c];
        #pragma unroll
        for(int nt=0; nt<4; nt++){
            uint2 bb = *(const uint2*)&w1_s[kc*512 + (wn*32 + nt*8 + q)*8 + 2*c];
            mma8(aD[nt], a0, a1, bb);
        }
    }
    #pragma unroll
    for(int nt=0; nt<4; nt++){
        int j0 = wn*32 + nt*8 + 2*c;
        float2 bb = *(const float2*)&b1g[j0];
        aD[nt][0] = fmaxf(aD[nt][0]+bb.x, 0.f);
        aD[nt][1] = fmaxf(aD[nt][1]+bb.y, 0.f);
        aD[nt][2] = fmaxf(aD[nt][2]+bb.x, 0.f);
        aD[nt][3] = fmaxf(aD[nt][3]+bb.y, 0.f);
    }

    // GEMM3: out = x @ Ws^T + dx  (accumulate into aD)
    #pragma unroll 4
    for(int kc=0; kc<16; kc++){
        uint2 a0 = *(const uint2*)&x_s[kc*512 + row0*8 + 2*c];
        uint2 a1 = *(const uint2*)&x_s[kc*512 + row1*8 + 2*c];
        #pragma unroll
        for(int nt=0; nt<4; nt++){
            uint2 bb = *(const uint2*)&ws_s[kc*512 + (wn*32 + nt*8 + q)*8 + 2*c];
            mma8(aD[nt], a0, a1, bb);
        }
    }

    // store natural fp32
    #pragma unroll
    for(int nt=0; nt<4; nt++){
        int j0 = wn*32 + nt*8 + 2*c;
        if(row0 < npts)
            *(float2*)&g_net[(gbase+row0)*HID + j0] = make_float2(aD[nt][0], aD[nt][1]);
        if(row1 < npts)
            *(float2*)&g_net[(gbase+row1)*HID + j0] = make_float2(aD[nt][2], aD[nt][3]);
    }
}

// ---------------- pooling scatter / normalize ----------------
__global__ void k_scatter_net(){
    int i = blockIdx.x*256 + threadIdx.x;
    if(i >= BN*HID) return;
    int ch = i & 63, pt = i >> 6;
    int b = pt / NP;
    int bin = g_idx[pt];
    atomicAdd(&g_binsum[(b*R2 + bin)*HID + ch], g_net[i]);
    if(ch == 0) atomicAdd(&g_bincnt[b*R2 + bin], 1.0f);
}

__global__ void k_poolnorm(){
    int i = blockIdx.x*256 + threadIdx.x;
    if(i >= BATCH*R2*HID) return;
    g_binsum[i] /= fmaxf(g_bincnt[i>>6], 1.0f);
}

// ---------------- final-net scatter to 3 planes ----------------
__global__ void k_scatter_net3(){
    int i = blockIdx.x*256 + threadIdx.x;
    if(i >= 3*BN*HID) return;
    int ch = i & 63, r = i >> 6;
    int pl = r / BN, pt = r - pl*BN;
    int b = pt / NP;
    int row = (pl*BATCH + b)*R2 + g_idx[pl*BN + pt];
    atomicAdd(&g_nsum[row*HID + ch], g_net[pt*HID + ch]);
    if(ch == 0) atomicAdd(&g_cnt3[row], 1.0f);
}

// ---------------- bin GEMM: fea = gate(cnt) * ((nsum/max(cnt,1)) @ Wc^T + bc), permuted tf32 ----------------
#define SM_FCC ((64*68 + 64*260)*4)
__global__ void k_fcc_bins(const float* __restrict__ Wc, const float* __restrict__ bc){
    extern __shared__ float sm[];
    float* x_s = sm;             // [64][68]
    float* wct = sm + 64*68;     // [64][260]
    int t = threadIdx.x;
    int r0 = blockIdx.x*64;
    for(int e=t; e<64*64; e+=256){
        int pt = e>>6, k = e&63;
        int row = r0 + pt;
        float cnt = g_cnt3[row];
        x_s[pt*68+k] = g_nsum[row*HID + k] / fmaxf(cnt, 1.0f);
    }
    for(int e=t; e<256*64; e+=256){
        int o = e>>6, k = e&63;
        wct[k*260 + o] = Wc[e];
    }
    __syncthreads();
    const int iperm[8] = {0,2,4,6,1,3,5,7};
    int og = t & 15, pbase = (t>>4)*4;
    for(int oc4=0; oc4<4; oc4++){
        int o0 = oc4*64 + og*4;
        float acc[4][4];
        #pragma unroll
        for(int i=0;i<4;i++){ acc[i][0]=acc[i][1]=acc[i][2]=acc[i][3]=0.f; }
        #pragma unroll 4
        for(int k=0;k<64;k++){
            float4 w = *(const float4*)&wct[k*260 + o0];
            #pragma unroll
            for(int i=0;i<4;i++){
                float xv = x_s[(pbase+i)*68 + k];
                acc[i][0]+=w.x*xv; acc[i][1]+=w.y*xv; acc[i][2]+=w.z*xv; acc[i][3]+=w.w*xv;
            }
        }
        float c0=bc[o0],c1=bc[o0+1],c2=bc[o0+2],c3=bc[o0+3];
        int jb = o0 & 7;
        #pragma unroll
        for(int i=0;i<4;i++){
            int row = r0 + pbase + i;
            float gate = (g_cnt3[row] > 0.f) ? 1.f : 0.f;
            float* d = &g_fea[row*FD + (o0 & ~7)];
            d[iperm[jb+0]] = totf(gate*(acc[i][0]+c0));
            d[iperm[jb+1]] = totf(gate*(acc[i][1]+c1));
            d[iperm[jb+2]] = totf(gate*(acc[i][2]+c2));
            d[iperm[jb+3]] = totf(gate*(acc[i][3]+c3));
        }
    }
}

// ---------------- conv weight prep: tf32 + fragment permuted ----------------
__global__ void k_wtrans(const float* __restrict__ Wa, const float* __restrict__ Wb){
    int i = blockIdx.x*256 + threadIdx.x;
    if(i >= 2*2304*FD) return;
    int cI = i / (2304*FD);
    int rem = i - cI*(2304*FD);
    int j  = rem & 7;
    int r2 = rem >> 3;
    int oc = r2 & 255;
    int r3 = r2 >> 8;
    int kk = r3 % 9, ch = r3 / 9;
    const int perm[8] = {0,4,1,5,2,6,3,7};
    int ic = ch*8 + perm[j];
    const float* W = cI ? Wb : Wa;
    g_wt[i] = totf(W[oc*2304 + ic*9 + kk]);
}

// ---------------- 3x3 conv 256->256 (+bias, relu), TF32 mma, cp.async double-buffered ----------------
#define SM_CONV ((2*2112 + 2*9216)*4)

__global__ void __launch_bounds__(256) k_conv(
        const float* __restrict__ in, float* __restrict__ out,
        const float* __restrict__ wt, const float* __restrict__ bias, int permout)
{
    extern __shared__ float sm[];
    float* ibuf = sm;              // [2][264*8]
    float* wbuf = sm + 2*2112;     // [2][9*128*8]
    unsigned ib_u = (unsigned)__cvta_generic_to_shared(ibuf);
    unsigned wb_u = (unsigned)__cvta_generic_to_shared(wbuf);
    int t = threadIdx.x;
    int lane = t & 31, w = t >> 5;
    int wm = w & 3, wn = w >> 2;
    int q = lane >> 2, c = lane & 3;

    int ocb = blockIdx.x & 1;
    int r = blockIdx.x >> 1;
    int rp = r & 31;
    int pb = r >> 5;
    const float* inp  = in  + pb*R2*FD;
    float*       outp = out + pb*R2*FD;
    int y0 = rp*2;
    int px_base = wm*32;

    float acc[2][8][4];
    #pragma unroll
    for(int mt=0; mt<2; mt++)
        #pragma unroll
        for(int nt=0; nt<8; nt++){
            acc[mt][nt][0]=0.f; acc[mt][nt][1]=0.f; acc[mt][nt][2]=0.f; acc[mt][nt][3]=0.f;
        }

    auto stage = [&](int ch, int buf){
        for(int e=t; e<528; e+=256){
            int pos = e>>1, half = e&1;
            int rr = pos/66, cc = pos - rr*66;
            int yy = y0 + rr - 1, xx = cc - 1;
            bool ok = (yy >= 0 && yy < 64 && (unsigned)xx < 64u);
            const float* src = inp + ((ok ? (yy*64+xx) : 0)*FD + ch*8 + half*4);
            cpa(ib_u + (unsigned)(buf*2112*4 + pos*32 + half*16), src, ok ? 16 : 0);
        }
        const float* wsrc = wt + (size_t)ch*18432 + ocb*1024;
        for(int e=t; e<2304; e+=256){
            int kk = e>>8, rem = e&255;
            cpa(wb_u + (unsigned)(buf*9216*4 + kk*4096 + rem*16),
                wsrc + kk*2048 + rem*4, 16);
        }
        CP_COMMIT;
    };

    stage(0, 0);
    for(int ch=0; ch<32; ch++){
        int cur = ch & 1;
        CP_WAIT0;
        __syncthreads();
        if(ch < 31) stage(ch+1, 1-cur);
        const float* in_s = ibuf + cur*2112;
        const float* w_s  = wbuf + cur*9216;
        #pragma unroll
        for(int kk=0; kk<9; kk++){
            int ky = kk/3, kx = kk - ky*3;
            uint2 a[2][2];
            #pragma unroll
            for(int mt=0; mt<2; mt++){
                int px0 = px_base + mt*16 + q;
                a[mt][0] = *(const uint2*)&in_s[(((px0>>6)+ky)*66 + (px0&63)+kx)*8 + 2*c];
                int px1 = px0 + 8;
                a[mt][1] = *(const uint2*)&in_s[(((px1>>6)+ky)*66 + (px1&63)+kx)*8 + 2*c];
            }
            const float* wb = &w_s[kk*1024 + (wn*64 + q)*8 + 2*c];
            #pragma unroll
            for(int nt=0; nt<8; nt++){
                uint2 b = *(const uint2*)&wb[nt*64];
                mma8(acc[0][nt], a[0][0], a[0][1], b);
                mma8(acc[1][nt], a[1][0], a[1][1], b);
            }
        }
        __syncthreads();
    }

    int o_base = ocb*128 + wn*64;
    const int iperm[8] = {0,2,4,6,1,3,5,7};
    #pragma unroll
    for(int nt=0; nt<8; nt++){
        int oc = o_base + nt*8 + 2*c;
        float2 bb = *(const float2*)&bias[oc];
        #pragma unroll
        for(int mt=0; mt<2; mt++){
            #pragma unroll
            for(int half=0; half<2; half++){
                int px = px_base + mt*16 + q + half*8;
                int y = y0 + (px>>6), x = px&63;
                float v0 = fmaxf(acc[mt][nt][half*2+0]+bb.x, 0.f);
                float v1 = fmaxf(acc[mt][nt][half*2+1]+bb.y, 0.f);
                float* d = &outp[(y*64+x)*FD];
                if(permout){
                    d[(oc & ~7) + iperm[2*c]]   = totf(v0);
                    d[(oc & ~7) + iperm[2*c+1]] = totf(v1);
                } else {
                    *(float2*)&d[oc] = make_float2(v0, v1);
                }
            }
        }
    }
}

// ---------------- bilinear grid sample over 3 planes, accumulate ----------------
__global__ void k_sample(const float* __restrict__ query, float* __restrict__ out){
    int gid = blockIdx.x*256 + threadIdx.x;
    int w = gid >> 5, lane = gid & 31;
    if(w >= BN) return;
    int b = w / NP;
    float q0 = query[w*3+0], q1 = query[w*3+1], q2 = query[w*3+2];
    float a0[4] = {0,0,0,0}, a1[4] = {0,0,0,0};
    #pragma unroll
    for(int pl=0; pl<3; pl++){
        float qa = (pl==2) ? q1 : q0;
        float qb = (pl==1) ? q1 : q2;
        float gx = qa*2.0f - 1.0f, gy = qb*2.0f - 1.0f;
        float x = ((gx + 1.0f)*64.0f - 1.0f)*0.5f;
        float y = ((gy + 1.0f)*64.0f - 1.0f)*0.5f;
        x = fminf(fmaxf(x, 0.0f), 63.0f);
        y = fminf(fmaxf(y, 0.0f), 63.0f);
        float x0f = floorf(x), y0f = floorf(y);
        int x0 = (int)x0f, y0 = (int)y0f;
        int x1 = min(x0+1, 63), y1 = min(y0+1, 63);
        float wx = x - x0f, wy = y - y0f;
        const float* f = &g_fec[(pl*BATCH + b)*R2*FD];
        float ww[4] = {(1.f-wx)*(1.f-wy), wx*(1.f-wy), (1.f-wx)*wy, wx*wy};
        int pix[4] = {y0*64+x0, y0*64+x1, y1*64+x0, y1*64+x1};
        #pragma unroll
        for(int tp=0; tp<4; tp++){
            const float* base = f + pix[tp]*FD;
            float4 v0 = *(const float4*)&base[lane*4];
            float4 v1 = *(const float4*)&base[128 + lane*4];
            float g = ww[tp];
            a0[0]+=g*v0.x; a0[1]+=g*v0.y; a0[2]+=g*v0.z; a0[3]+=g*v0.w;
            a1[0]+=g*v1.x; a1[1]+=g*v1.y; a1[2]+=g*v1.z; a1[3]+=g*v1.w;
        }
    }
    float* ob = &out[w*FD];
    *(float4*)&ob[lane*4]       = make_float4(a0[0],a0[1],a0[2],a0[3]);
    *(float4*)&ob[128+lane*4]   = make_float4(a1[0],a1[1],a1[2],a1[3]);
}

// ---------------- launch ----------------
extern "C" void kernel_launch(void* const* d_in, const int* in_sizes, int n_in,
                              void* d_out, int out_size)
{
    const float* p    = (const float*)d_in[0];
    const float* qry  = (const float*)d_in[1];
    const float* fcW  = (const float*)d_in[2];
    const float* fcb  = (const float*)d_in[3];
    const float* W0   = (const float*)d_in[4];
    const float* b0   = (const float*)d_in[5];
    const float* W1   = (const float*)d_in[6];
    const float* b1   = (const float*)d_in[7];
    const float* Ws   = (const float*)d_in[8];
    const float* Wc   = (const float*)d_in[9];
    const float* bc   = (const float*)d_in[10];
    const float* C1W  = (const float*)d_in[11];
    const float* C1b  = (const float*)d_in[12];
    const float* C2W  = (const float*)d_in[13];
    const float* C2b  = (const float*)d_in[14];
    float* out = (float*)d_out;

    cudaFuncSetAttribute(k_block,    cudaFuncAttributeMaxDynamicSharedMemorySize, SM_BLOCK);
    cudaFuncSetAttribute(k_fcc_bins, cudaFuncAttributeMaxDynamicSharedMemorySize, SM_FCC);
    cudaFuncSetAttribute(k_conv,     cudaFuncAttributeMaxDynamicSharedMemorySize, SM_CONV);

    void *binsum_p, *bincnt_p, *nsum_p, *cnt3_p, *fea_p, *feb_p, *fec_p, *wt_p;
    cudaGetSymbolAddress(&binsum_p, g_binsum);
    cudaGetSymbolAddress(&bincnt_p, g_bincnt);
    cudaGetSymbolAddress(&nsum_p,   g_nsum);
    cudaGetSymbolAddress(&cnt3_p,   g_cnt3);
    cudaGetSymbolAddress(&fea_p,    g_fea);
    cudaGetSymbolAddress(&feb_p,    g_feb);
    cudaGetSymbolAddress(&fec_p,    g_fec);
    cudaGetSymbolAddress(&wt_p,     g_wt);

    k_idx<<<(BN+255)/256, 256>>>(p);
    k_wtrans<<<(2*2304*FD)/256, 256>>>(C1W, C2W);
    k_wblk<<<(3*20480+255)/256, 256>>>(W0, W1, Ws);

    k_block<<<BATCH*NT, 256, SM_BLOCK>>>(0, p, fcW, fcb, b0, b1);

    for(int it=1; it<=2; it++){
        cudaMemsetAsync(binsum_p, 0, (size_t)BATCH*R2*HID*4);
        cudaMemsetAsync(bincnt_p, 0, (size_t)BATCH*R2*4);
        k_scatter_net<<<(BN*HID+255)/256, 256>>>();
        k_poolnorm<<<(BATCH*R2*HID+255)/256, 256>>>();
        k_block<<<BATCH*NT, 256, SM_BLOCK>>>(it, p, fcW, fcb, b0 + it*HID, b1 + it*HID);
    }

    cudaMemsetAsync(nsum_p, 0, (size_t)NBROW*HID*4);
    cudaMemsetAsync(cnt3_p, 0, (size_t)NBROW*4);
    k_scatter_net3<<<(3*BN*HID+255)/256, 256>>>();
    k_fcc_bins<<<NBROW/64, 256, SM_FCC>>>(Wc, bc);

    k_conv<<<12*32*2, 256, SM_CONV>>>((const float*)fea_p, (float*)feb_p,
                                      (const float*)wt_p,               C1b, 1);
    k_conv<<<12*32*2, 256, SM_CONV>>>((const float*)feb_p, (float*)fec_p,
                                      (const float*)wt_p + 2304*FD,     C2b, 0);

    k_sample<<<(BN*32)/256, 256>>>(qry, out);
}

// round 6
// speedup vs baseline: 3.4490x; 1.0416x over previous
#include <cuda_runtime.h>

#define BATCH 4
#define NP 30000
#define BN (BATCH*NP)
#define HID 64
#define FD 256
#define R2 4096
#define NT2 235  /* ceil(NP/128) */
#define NBROW (3*BATCH*R2)

// ---------------- scratch (no allocation allowed) ----------------
__device__ float g_net[BN*HID];
__device__ int   g_idx[3*BN];
__device__ float g_binsum[BATCH*R2*HID];
__device__ float g_bincnt[BATCH*R2];
__device__ float g_nsum[NBROW*HID];
__device__ float g_cnt3[NBROW];
__device__ __align__(128) float g_fea[NBROW*FD];     // conv1 in  (permuted tf32)
__device__ __align__(128) float g_feb[NBROW*FD];     // conv1 out (permuted tf32)
__device__ __align__(128) float g_fec[NBROW*FD];     // conv2 out (natural fp32)
__device__ __align__(128) float g_wt[2*2304*FD];     // conv tf32 wt
__device__ __align__(128) float g_wblk[3*20480];     // resblock tf32 wt per mode
__device__ __align__(128) float g_wfcc[16384];       // fc_c tf32 wt [8kc][256n][8s]

// ---------------- helpers ----------------
__device__ __forceinline__ float totf(float x){
    unsigned u; asm("cvt.rna.tf32.f32 %0, %1;" : "=r"(u) : "f"(x));
    return __uint_as_float(u);
}
__device__ __forceinline__ void cpa(unsigned d, const void* s, int sz){
    asm volatile("cp.async.cg.shared.global [%0], [%1], 16, %2;" :: "r"(d), "l"(s), "r"(sz));
}
#define CP_COMMIT asm volatile("cp.async.commit_group;")
#define CP_WAIT0  asm volatile("cp.async.wait_group 0;")

__device__ __forceinline__ void mma8(float* d, uint2 ar0, uint2 ar1, uint2 b){
    asm volatile("mma.sync.aligned.m16n8k8.row.col.f32.tf32.tf32.f32 "
        "{%0,%1,%2,%3}, {%4,%5,%6,%7}, {%8,%9}, {%0,%1,%2,%3};"
        : "+f"(d[0]),"+f"(d[1]),"+f"(d[2]),"+f"(d[3])
        : "r"(ar0.x),"r"(ar1.x),"r"(ar0.y),"r"(ar1.y), "r"(b.x),"r"(b.y));
}

// ---------------- bin indices ----------------
__device__ __forceinline__ int binof(float v){
    const float DEN = (float)(1.0 + 0.1 + 1e-6);
    float w = (v + 0.5f) / DEN;
    w = fminf(fmaxf(w, 0.0f), (float)(1.0 - 1e-6));
    return (int)(w * 64.0f);
}

__global__ void k_idx(const float* __restrict__ p){
    int i = blockIdx.x*256 + threadIdx.x;
    if(i >= BN) return;
    float x = p[i*3+0], y = p[i*3+1], z = p[i*3+2];
    int bx = binof(x), by = binof(y), bz = binof(z);
    g_idx[0*BN+i] = bx + 64*bz;
    g_idx[1*BN+i] = bx + 64*by;
    g_idx[2*BN+i] = by + 64*bz;
}

// ---------------- resblock weight prep ----------------
__global__ void k_wblk(const float* __restrict__ W0, const float* __restrict__ W1,
                       const float* __restrict__ Ws){
    int i = blockIdx.x*256 + threadIdx.x;
    if(i >= 3*20480) return;
    int m = i / 20480, r = i - m*20480;
    const float* src; int kc, n, s, K;
    if(r < 8192){ src = W0 + m*64*128; kc = r>>9; n = (r>>3)&63; s = r&7; K = 128; }
    else if(r < 12288){ int q = r-8192; src = W1 + m*64*64; kc = q>>9; n = (q>>3)&63; s = q&7; K = 64; }
    else { int q = r-12288; src = Ws + m*64*128; kc = q>>9; n = (q>>3)&63; s = q&7; K = 128; }
    int k = kc*8 + (s&1)*4 + (s>>1);
    g_wblk[i] = totf(src[n*K + k]);
}

// ---------------- fc_c weight prep: Wc[256][64] -> [8kc][256n][8s] tf32 ----------------
__global__ void k_wfcc(const float* __restrict__ Wc){
    int i = blockIdx.x*256 + threadIdx.x;
    if(i >= 16384) return;
    int s = i & 7, n = (i>>3)&255, kc = i>>11;
    int k = kc*8 + (s&1)*4 + (s>>1);
    g_wfcc[i] = totf(Wc[n*64 + k]);
}

// ---------------- fused resblock, TF32 mma, 128-pt tiles, warp 32x32 ----------------
#define SM_BLOCK ((16384 + 8192 + 20480)*4)

__global__ void __launch_bounds__(256) k_block(int mode, const float* __restrict__ p,
                        const float* __restrict__ fcW, const float* __restrict__ fcb,
                        const float* __restrict__ b0g, const float* __restrict__ b1g)
{
    extern __shared__ float sm[];
    float* x_s  = sm;              // [16 kc][128 pt][8]
    float* h_s  = sm + 16384;      // [8 kc][128 pt][8]
    float* wall = sm + 24576;      // 20480: w0 [16kc][64n][8] | w1 [8kc][64n][8] | ws
    float* w0_s = wall;
    float* w1_s = wall + 8192;
    float* ws_s = wall + 12288;
    unsigned wall_u = (unsigned)__cvta_generic_to_shared(wall);

    int t = threadIdx.x;
    int lane = t & 31, w = t >> 5;
    int wm = w & 3, wn = w >> 2;
    int q = lane >> 2, c = lane & 3;
    int s0 = (c < 2) ? 4*c     : 4*c - 7;
    int s1 = (c < 2) ? 4*c + 2 : 4*c - 5;

    int b = blockIdx.x / NT2, tile = blockIdx.x % NT2;
    int pt0 = tile*128;
    int npts = min(128, NP - pt0);
    int gbase = b*NP + pt0;

    {
        const float* wsrc = g_wblk + mode*20480;
        for(int e=t; e<5120; e+=256)
            cpa(wall_u + (unsigned)e*16, wsrc + e*4, 16);
        CP_COMMIT;
    }

    // stage x tile: 128 pt x 16 kc x 2 half
    if(mode == 0){
        for(int e=t; e<4096; e+=256){
            int pt = e>>5, g = e&31;
            int kc = g>>1, half = g&1;
            int kb = kc*8 + half*4;
            float* d = &x_s[kc*1024 + pt*8 + half];
            if(pt < npts){
                int gp = (gbase + pt)*3;
                float px = p[gp], py = p[gp+1], pz = p[gp+2];
                #pragma unroll
                for(int i2=0;i2<4;i2++){
                    int j = kb + i2;
                    float v = fcb[j] + px*fcW[j*3] + py*fcW[j*3+1] + pz*fcW[j*3+2];
                    d[2*i2] = totf(v);
                }
            } else {
                d[0]=0.f; d[2]=0.f; d[4]=0.f; d[6]=0.f;
            }
        }
    } else {
        for(int e=t; e<4096; e+=256){
            int pt = e>>5, g = e&31;
            int kc = g>>1, half = g&1;
            float4 v = make_float4(0.f,0.f,0.f,0.f);
            if(pt < npts){
                int gi = gbase + pt;
                if(kc < 8) v = *(const float4*)&g_net[gi*HID + kc*8 + half*4];
                else       v = *(const float4*)&g_binsum[(b*R2 + g_idx[gi])*HID + (kc-8)*8 + half*4];
            }
            float* d = &x_s[kc*1024 + pt*8 + half];
            d[0]=totf(v.x); d[2]=totf(v.y); d[4]=totf(v.z); d[6]=totf(v.w);
        }
    }
    CP_WAIT0;
    __syncthreads();

    int rb = wm*32;

    // GEMM1: h = relu(x @ W0^T + b0)
    float aH[2][4][4];
    #pragma unroll
    for(int mt=0;mt<2;mt++)
        #pragma unroll
        for(int nt=0;nt<4;nt++){ aH[mt][nt][0]=aH[mt][nt][1]=aH[mt][nt][2]=aH[mt][nt][3]=0.f; }
    #pragma unroll 4
    for(int kc=0; kc<16; kc++){
        uint2 a[2][2];
        #pragma unroll
        for(int mt=0;mt<2;mt++){
            a[mt][0] = *(const uint2*)&x_s[kc*1024 + (rb+mt*16+q)*8 + 2*c];
            a[mt][1] = *(const uint2*)&x_s[kc*1024 + (rb+mt*16+q+8)*8 + 2*c];
        }
        #pragma unroll
        for(int nt=0; nt<4; nt++){
            uint2 bb = *(const uint2*)&w0_s[kc*512 + (wn*32 + nt*8 + q)*8 + 2*c];
            mma8(aH[0][nt], a[0][0], a[0][1], bb);
            mma8(aH[1][nt], a[1][0], a[1][1], bb);
        }
    }
    #pragma unroll
    for(int nt=0; nt<4; nt++){
        int j0 = wn*32 + nt*8 + 2*c;
        float2 bb = *(const float2*)&b0g[j0];
        float* dl = &h_s[(j0>>3)*1024];
        #pragma unroll
        for(int mt=0;mt<2;mt++){
            int r0m = rb + mt*16 + q, r1m = r0m + 8;
            dl[r0m*8 + s0] = totf(fmaxf(aH[mt][nt][0]+bb.x, 0.f));
            dl[r0m*8 + s1] = totf(fmaxf(aH[mt][nt][1]+bb.y, 0.f));
            dl[r1m*8 + s0] = totf(fmaxf(aH[mt][nt][2]+bb.x, 0.f));
            dl[r1m*8 + s1] = totf(fmaxf(aH[mt][nt][3]+bb.y, 0.f));
        }
    }
    __syncthreads();

    // GEMM2: dx = relu(h @ W1^T + b1)
    float aD[2][4][4];
    #pragma unroll
    for(int mt=0;mt<2;mt++)
        #pragma unroll
        for(int nt=0;nt<4;nt++){ aD[mt][nt][0]=aD[mt][nt][1]=aD[mt][nt][2]=aD[mt][nt][3]=0.f; }
    #pragma unroll 4
    for(int kc=0; kc<8; kc++){
        uint2 a[2][2];
        #pragma unroll
        for(int mt=0;mt<2;mt++){
            a[mt][0] = *(const uint2*)&h_s[kc*1024 + (rb+mt*16+q)*8 + 2*c];
            a[mt][1] = *(const uint2*)&h_s[kc*1024 + (rb+mt*16+q+8)*8 + 2*c];
        }
        #pragma unroll
        for(int nt=0; nt<4; nt++){
            uint2 bb = *(const uint2*)&w1_s[kc*512 + (wn*32 + nt*8 + q)*8 + 2*c];
            mma8(aD[0][nt], a[0][0], a[0][1], bb);
            mma8(aD[1][nt], a[1][0], a[1][1], bb);
        }
    }
    #pragma unroll
    for(int nt=0; nt<4; nt++){
        int j0 = wn*32 + nt*8 + 2*c;
        float2 bb = *(const float2*)&b1g[j0];
        #pragma unroll
        for(int mt=0;mt<2;mt++){
            aD[mt][nt][0] = fmaxf(aD[mt][nt][0]+bb.x, 0.f);
            aD[mt][nt][1] = fmaxf(aD[mt][nt][1]+bb.y, 0.f);
            aD[mt][nt][2] = fmaxf(aD[mt][nt][2]+bb.x, 0.f);
            aD[mt][nt][3] = fmaxf(aD[mt][nt][3]+bb.y, 0.f);
        }
    }

    // GEMM3: out = x @ Ws^T + dx
    #pragma unroll 4
    for(int kc=0; kc<16; kc++){
        uint2 a[2][2];
        #pragma unroll
        for(int mt=0;mt<2;mt++){
            a[mt][0] = *(const uint2*)&x_s[kc*1024 + (rb+mt*16+q)*8 + 2*c];
            a[mt][1] = *(const uint2*)&x_s[kc*1024 + (rb+mt*16+q+8)*8 + 2*c];
        }
        #pragma unroll
        for(int nt=0; nt<4; nt++){
            uint2 bb = *(const uint2*)&ws_s[kc*512 + (wn*32 + nt*8 + q)*8 + 2*c];
            mma8(aD[0][nt], a[0][0], a[0][1], bb);
            mma8(aD[1][nt], a[1][0], a[1][1], bb);
        }
    }

    #pragma unroll
    for(int nt=0; nt<4; nt++){
        int j0 = wn*32 + nt*8 + 2*c;
        #pragma unroll
        for(int mt=0;mt<2;mt++){
            int r0m = rb + mt*16 + q, r1m = r0m + 8;
            if(r0m < npts)
                *(float2*)&g_net[(gbase+r0m)*HID + j0] = make_float2(aD[mt][nt][0], aD[mt][nt][1]);
            if(r1m < npts)
                *(float2*)&g_net[(gbase+r1m)*HID + j0] = make_float2(aD[mt][nt][2], aD[mt][nt][3]);
        }
    }
}

// ---------------- pooling scatter / normalize ----------------
__global__ void k_scatter_net(){
    int i = blockIdx.x*256 + threadIdx.x;
    if(i >= BN*HID) return;
    int ch = i & 63, pt = i >> 6;
    int b = pt / NP;
    int bin = g_idx[pt];
    atomicAdd(&g_binsum[(b*R2 + bin)*HID + ch], g_net[i]);
    if(ch == 0) atomicAdd(&g_bincnt[b*R2 + bin], 1.0f);
}

__global__ void k_poolnorm(){
    int i = blockIdx.x*256 + threadIdx.x;
    if(i >= BATCH*R2*HID) return;
    g_binsum[i] /= fmaxf(g_bincnt[i>>6], 1.0f);
}

// ---------------- final-net scatter to 3 planes ----------------
__global__ void k_scatter_net3(){
    int i = blockIdx.x*256 + threadIdx.x;
    if(i >= 3*BN*HID) return;
    int ch = i & 63, r = i >> 6;
    int pl = r / BN, pt = r - pl*BN;
    int b = pt / NP;
    int row = (pl*BATCH + b)*R2 + g_idx[pl*BN + pt];
    atomicAdd(&g_nsum[row*HID + ch], g_net[pt*HID + ch]);
    if(ch == 0) atomicAdd(&g_cnt3[row], 1.0f);
}

// ---------------- bin GEMM fc_c (TF32 mma): fea = gate*(mean @ Wc^T + bc), permuted tf32 out ----------------
#define SM_FCC ((4096 + 16384)*4)
__global__ void __launch_bounds__(256) k_fcc_bins(const float* __restrict__ bc){
    extern __shared__ float sm[];
    float* x_s = sm;             // [8kc][64pt][8]
    float* w_s = sm + 4096;      // [8kc][256n][8]
    unsigned ws_u = (unsigned)__cvta_generic_to_shared(w_s);
    int t = threadIdx.x;
    int lane = t & 31, w = t >> 5;
    int wm = w & 1, wn = w >> 1;          // 2 M-warps x 4 N-warps
    int q = lane >> 2, c = lane & 3;
    int r0 = blockIdx.x*64;

    for(int e=t; e<4096; e+=256)
        cpa(ws_u + (unsigned)e*16, g_wfcc + e*4, 16);
    CP_COMMIT;

    // stage x: 64 pt x 8 kc x 2 half
    for(int e=t; e<1024; e+=256){
        int pt = e>>4, g = e&15;
        int kc = g>>1, half = g&1;
        int row = r0 + pt;
        float inv = 1.0f / fmaxf(g_cnt3[row], 1.0f);
        float4 v = *(const float4*)&g_nsum[row*HID + kc*8 + half*4];
        float* d = &x_s[kc*512 + pt*8 + half];
        d[0]=totf(v.x*inv); d[2]=totf(v.y*inv); d[4]=totf(v.z*inv); d[6]=totf(v.w*inv);
    }
    CP_WAIT0;
    __syncthreads();

    int rb = wm*32;
    float acc[2][8][4];
    #pragma unroll
    for(int mt=0;mt<2;mt++)
        #pragma unroll
        for(int nt=0;nt<8;nt++){ acc[mt][nt][0]=acc[mt][nt][1]=acc[mt][nt][2]=acc[mt][nt][3]=0.f; }
    #pragma unroll
    for(int kc=0; kc<8; kc++){
        uint2 a[2][2];
        #pragma unroll
        for(int mt=0;mt<2;mt++){
            a[mt][0] = *(const uint2*)&x_s[kc*512 + (rb+mt*16+q)*8 + 2*c];
            a[mt][1] = *(const uint2*)&x_s[kc*512 + (rb+mt*16+q+8)*8 + 2*c];
        }
        const float* wb = &w_s[kc*2048 + (wn*64 + q)*8 + 2*c];
        #pragma unroll
        for(int nt=0; nt<8; nt++){
            uint2 bb = *(const uint2*)&wb[nt*64];
            mma8(acc[0][nt], a[0][0], a[0][1], bb);
            mma8(acc[1][nt], a[1][0], a[1][1], bb);
        }
    }

    const int iperm[8] = {0,2,4,6,1,3,5,7};
    #pragma unroll
    for(int nt=0; nt<8; nt++){
        int j0 = wn*64 + nt*8 + 2*c;
        float2 bb = *(const float2*)&bc[j0];
        #pragma unroll
        for(int mt=0;mt<2;mt++){
            #pragma unroll
            for(int half=0; half<2; half++){
                int r = rb + mt*16 + q + half*8;
                int row = r0 + r;
                float gate = (g_cnt3[row] > 0.f) ? 1.f : 0.f;
                float* d = &g_fea[row*FD + (j0 & ~7)];
                d[iperm[2*c]]   = totf(gate*(acc[mt][nt][half*2+0]+bb.x));
                d[iperm[2*c+1]] = totf(gate*(acc[mt][nt][half*2+1]+bb.y));
            }
        }
    }
}

// ---------------- conv weight prep ----------------
__global__ void k_wtrans(const float* __restrict__ Wa, const float* __restrict__ Wb){
    int i = blockIdx.x*256 + threadIdx.x;
    if(i >= 2*2304*FD) return;
    int cI = i / (2304*FD);
    int rem = i - cI*(2304*FD);
    int j  = rem & 7;
    int r2 = rem >> 3;
    int oc = r2 & 255;
    int r3 = r2 >> 8;
    int kk = r3 % 9, ch = r3 / 9;
    const int perm[8] = {0,4,1,5,2,6,3,7};
    int ic = ch*8 + perm[j];
    const float* W = cI ? Wb : Wa;
    g_wt[i] = totf(W[oc*2304 + ic*9 + kk]);
}

// ---------------- 3x3 conv 256->256 (+bias, relu), TF32 mma, cp.async double-buffered ----------------
#define SM_CONV ((2*2112 + 2*9216)*4)

__global__ void __launch_bounds__(256) k_conv(
        const float* __restrict__ in, float* __restrict__ out,
        const float* __restrict__ wt, const float* __restrict__ bias, int permout)
{
    extern __shared__ float sm[];
    float* ibuf = sm;
    float* wbuf = sm + 2*2112;
    unsigned ib_u = (unsigned)__cvta_generic_to_shared(ibuf);
    unsigned wb_u = (unsigned)__cvta_generic_to_shared(wbuf);
    int t = threadIdx.x;
    int lane = t & 31, w = t >> 5;
    int wm = w & 3, wn = w >> 2;
    int q = lane >> 2, c = lane & 3;

    int ocb = blockIdx.x & 1;
    int r = blockIdx.x >> 1;
    int rp = r & 31;
    int pb = r >> 5;
    const float* inp  = in  + pb*R2*FD;
    float*       outp = out + pb*R2*FD;
    int y0 = rp*2;
    int px_base = wm*32;

    float acc[2][8][4];
    #pragma unroll
    for(int mt=0; mt<2; mt++)
        #pragma unroll
        for(int nt=0; nt<8; nt++){
            acc[mt][nt][0]=0.f; acc[mt][nt][1]=0.f; acc[mt][nt][2]=0.f; acc[mt][nt][3]=0.f;
        }

    auto stage = [&](int ch, int buf){
        for(int e=t; e<528; e+=256){
            int pos = e>>1, half = e&1;
            int rr = pos/66, cc = pos - rr*66;
            int yy = y0 + rr - 1, xx = cc - 1;
            bool ok = (yy >= 0 && yy < 64 && (unsigned)xx < 64u);
            const float* src = inp + ((ok ? (yy*64+xx) : 0)*FD + ch*8 + half*4);
            cpa(ib_u + (unsigned)(buf*2112*4 + pos*32 + half*16), src, ok ? 16 : 0);
        }
        const float* wsrc = wt + (size_t)ch*18432 + ocb*1024;
        for(int e=t; e<2304; e+=256){
            int kk = e>>8, rem = e&255;
            cpa(wb_u + (unsigned)(buf*9216*4 + kk*4096 + rem*16),
                wsrc + kk*2048 + rem*4, 16);
        }
        CP_COMMIT;
    };

    stage(0, 0);
    for(int ch=0; ch<32; ch++){
        int cur = ch & 1;
        CP_WAIT0;
        __syncthreads();
        if(ch < 31) stage(ch+1, 1-cur);
        const float* in_s = ibuf + cur*2112;
        const float* w_s  = wbuf + cur*9216;
        #pragma unroll
        for(int kk=0; kk<9; kk++){
            int ky = kk/3, kx = kk - ky*3;
            uint2 a[2][2];
            #pragma unroll
            for(int mt=0; mt<2; mt++){
                int px0 = px_base + mt*16 + q;
                a[mt][0] = *(const uint2*)&in_s[(((px0>>6)+ky)*66 + (px0&63)+kx)*8 + 2*c];
                int px1 = px0 + 8;
                a[mt][1] = *(const uint2*)&in_s[(((px1>>6)+ky)*66 + (px1&63)+kx)*8 + 2*c];
            }
            const float* wb = &w_s[kk*1024 + (wn*64 + q)*8 + 2*c];
            #pragma unroll
            for(int nt=0; nt<8; nt++){
                uint2 b = *(const uint2*)&wb[nt*64];
                mma8(acc[0][nt], a[0][0], a[0][1], b);
                mma8(acc[1][nt], a[1][0], a[1][1], b);
            }
        }
        __syncthreads();
    }

    int o_base = ocb*128 + wn*64;
    const int iperm[8] = {0,2,4,6,1,3,5,7};
    #pragma unroll
    for(int nt=0; nt<8; nt++){
        int oc = o_base + nt*8 + 2*c;
        float2 bb = *(const float2*)&bias[oc];
        #pragma unroll
        for(int mt=0; mt<2; mt++){
            #pragma unroll
            for(int half=0; half<2; half++){
                int px = px_base + mt*16 + q + half*8;
                int y = y0 + (px>>6), x = px&63;
                float v0 = fmaxf(acc[mt][nt][half*2+0]+bb.x, 0.f);
                float v1 = fmaxf(acc[mt][nt][half*2+1]+bb.y, 0.f);
                float* d = &outp[(y*64+x)*FD];
                if(permout){
                    d[(oc & ~7) + iperm[2*c]]   = totf(v0);
                    d[(oc & ~7) + iperm[2*c+1]] = totf(v1);
                } else {
                    *(float2*)&d[oc] = make_float2(v0, v1);
                }
            }
        }
    }
}

// ---------------- bilinear grid sample over 3 planes, accumulate ----------------
__global__ void k_sample(const float* __restrict__ query, float* __restrict__ out){
    int gid = blockIdx.x*256 + threadIdx.x;
    int w = gid >> 5, lane = gid & 31;
    if(w >= BN) return;
    int b = w / NP;
    float q0 = query[w*3+0], q1 = query[w*3+1], q2 = query[w*3+2];
    float a0[4] = {0,0,0,0}, a1[4] = {0,0,0,0};
    #pragma unroll
    for(int pl=0; pl<3; pl++){
        float qa = (pl==2) ? q1 : q0;
        float qb = (pl==1) ? q1 : q2;
        float gx = qa*2.0f - 1.0f, gy = qb*2.0f - 1.0f;
        float x = ((gx + 1.0f)*64.0f - 1.0f)*0.5f;
        float y = ((gy + 1.0f)*64.0f - 1.0f)*0.5f;
        x = fminf(fmaxf(x, 0.0f), 63.0f);
        y = fminf(fmaxf(y, 0.0f), 63.0f);
        float x0f = floorf(x), y0f = floorf(y);
        int x0 = (int)x0f, y0 = (int)y0f;
        int x1 = min(x0+1, 63), y1 = min(y0+1, 63);
        float wx = x - x0f, wy = y - y0f;
        const float* f = &g_fec[(pl*BATCH + b)*R2*FD];
        float ww[4] = {(1.f-wx)*(1.f-wy), wx*(1.f-wy), (1.f-wx)*wy, wx*wy};
        int pix[4] = {y0*64+x0, y0*64+x1, y1*64+x0, y1*64+x1};
        #pragma unroll
        for(int tp=0; tp<4; tp++){
            const float* base = f + pix[tp]*FD;
            float4 v0 = *(const float4*)&base[lane*4];
            float4 v1 = *(const float4*)&base[128 + lane*4];
            float g = ww[tp];
            a0[0]+=g*v0.x; a0[1]+=g*v0.y; a0[2]+=g*v0.z; a0[3]+=g*v0.w;
            a1[0]+=g*v1.x; a1[1]+=g*v1.y; a1[2]+=g*v1.z; a1[3]+=g*v1.w;
        }
    }
    float* ob = &out[w*FD];
    *(float4*)&ob[lane*4]       = make_float4(a0[0],a0[1],a0[2],a0[3]);
    *(float4*)&ob[128+lane*4]   = make_float4(a1[0],a1[1],a1[2],a1[3]);
}

// ---------------- launch ----------------
extern "C" void kernel_launch(void* const* d_in, const int* in_sizes, int n_in,
                              void* d_out, int out_size)
{
    const float* p    = (const float*)d_in[0];
    const float* qry  = (const float*)d_in[1];
    const float* fcW  = (const float*)d_in[2];
    const float* fcb  = (const float*)d_in[3];
    const float* W0   = (const float*)d_in[4];
    const float* b0   = (const float*)d_in[5];
    const float* W1   = (const float*)d_in[6];
    const float* b1   = (const float*)d_in[7];
    const float* Ws   = (const float*)d_in[8];
    const float* Wc   = (const float*)d_in[9];
    const float* bc   = (const float*)d_in[10];
    const float* C1W  = (const float*)d_in[11];
    const float* C1b  = (const float*)d_in[12];
    const float* C2W  = (const float*)d_in[13];
    const float* C2b  = (const float*)d_in[14];
    float* out = (float*)d_out;

    cudaFuncSetAttribute(k_block,    cudaFuncAttributeMaxDynamicSharedMemorySize, SM_BLOCK);
    cudaFuncSetAttribute(k_fcc_bins, cudaFuncAttributeMaxDynamicSharedMemorySize, SM_FCC);
    cudaFuncSetAttribute(k_conv,     cudaFuncAttributeMaxDynamicSharedMemorySize, SM_CONV);

    void *binsum_p, *bincnt_p, *nsum_p, *cnt3_p, *fea_p, *feb_p, *fec_p, *wt_p;
    cudaGetSymbolAddress(&binsum_p, g_binsum);
    cudaGetSymbolAddress(&bincnt_p, g_bincnt);
    cudaGetSymbolAddress(&nsum_p,   g_nsum);
    cudaGetSymbolAddress(&cnt3_p,   g_cnt3);
    cudaGetSymbolAddress(&fea_p,    g_fea);
    cudaGetSymbolAddress(&feb_p,    g_feb);
    cudaGetSymbolAddress(&fec_p,    g_fec);
    cudaGetSymbolAddress(&wt_p,     g_wt);

    k_idx<<<(BN+255)/256, 256>>>(p);
    k_wtrans<<<(2*2304*FD)/256, 256>>>(C1W, C2W);
    k_wblk<<<(3*20480+255)/256, 256>>>(W0, W1, Ws);
    k_wfcc<<<16384/256, 256>>>(Wc);

    k_block<<<BATCH*NT2, 256, SM_BLOCK>>>(0, p, fcW, fcb, b0, b1);

    for(int it=1; it<=2; it++){
        cudaMemsetAsync(binsum_p, 0, (size_t)BATCH*R2*HID*4);
        cudaMemsetAsync(bincnt_p, 0, (size_t)BATCH*R2*4);
        k_scatter_net<<<(BN*HID+255)/256, 256>>>();
        k_poolnorm<<<(BATCH*R2*HID+255)/256, 256>>>();
        k_block<<<BATCH*NT2, 256, SM_BLOCK>>>(it, p, fcW, fcb, b0 + it*HID, b1 + it*HID);
    }

    cudaMemsetAsync(nsum_p, 0, (size_t)NBROW*HID*4);
    cudaMemsetAsync(cnt3_p, 0, (size_t)NBROW*4);
    k_scatter_net3<<<(3*BN*HID+255)/256, 256>>>();
    k_fcc_bins<<<NBROW/64, 256, SM_FCC>>>(bc);

    k_conv<<<12*32*2, 256, SM_CONV>>>((const float*)fea_p, (float*)feb_p,
                                      (const float*)wt_p,               C1b, 1);
    k_conv<<<12*32*2, 256, SM_CONV>>>((const float*)feb_p, (float*)fec_p,
                                      (const float*)wt_p + 2304*FD,     C2b, 0);

    k_sample<<<(BN*32)/256, 256>>>(qry, out);
}

// round 7
// speedup vs baseline: 3.6004x; 1.0439x over previous
#include <cuda_runtime.h>

#define BATCH 4
#define NP 30000
#define BN (BATCH*NP)
#define HID 64
#define FD 256
#define R2 4096
#define NT2 235  /* ceil(NP/128) */
#define NBROW (3*BATCH*R2)

// ---------------- scratch (no allocation allowed) ----------------
__device__ float g_net[BN*HID];
__device__ int   g_idx[3*BN];
__device__ float g_binsum2[2*BATCH*R2*HID];   // ping-pong raw bin sums (xz pooling)
__device__ float g_bincnt2[2*BATCH*R2];
__device__ float g_nsum[NBROW*HID];
__device__ float g_cnt3[NBROW];
__device__ __align__(128) float g_fea[NBROW*FD];     // conv1 in  (permuted tf32)
__device__ __align__(128) float g_feb[NBROW*FD];     // conv1 out (permuted tf32)
__device__ __align__(128) float g_fec[NBROW*FD];     // conv2 out (natural fp32)
__device__ __align__(128) float g_wt[2*2304*FD];     // conv tf32 wt
__device__ __align__(128) float g_wblk[3*20480];     // resblock tf32 wt per mode
__device__ __align__(128) float g_wfcc[16384];       // fc_c tf32 wt [8kc][256n][8s]

// ---------------- helpers ----------------
__device__ __forceinline__ float totf(float x){
    unsigned u; asm("cvt.rna.tf32.f32 %0, %1;" : "=r"(u) : "f"(x));
    return __uint_as_float(u);
}
__device__ __forceinline__ void cpa(unsigned d, const void* s, int sz){
    asm volatile("cp.async.cg.shared.global [%0], [%1], 16, %2;" :: "r"(d), "l"(s), "r"(sz));
}
#define CP_COMMIT asm volatile("cp.async.commit_group;")
#define CP_WAIT0  asm volatile("cp.async.wait_group 0;")

__device__ __forceinline__ void mma8(float* d, uint2 ar0, uint2 ar1, uint2 b){
    asm volatile("mma.sync.aligned.m16n8k8.row.col.f32.tf32.tf32.f32 "
        "{%0,%1,%2,%3}, {%4,%5,%6,%7}, {%8,%9}, {%0,%1,%2,%3};"
        : "+f"(d[0]),"+f"(d[1]),"+f"(d[2]),"+f"(d[3])
        : "r"(ar0.x),"r"(ar1.x),"r"(ar0.y),"r"(ar1.y), "r"(b.x),"r"(b.y));
}

// ---------------- bin indices ----------------
__device__ __forceinline__ int binof(float v){
    const float DEN = (float)(1.0 + 0.1 + 1e-6);
    float w = (v + 0.5f) / DEN;
    w = fminf(fmaxf(w, 0.0f), (float)(1.0 - 1e-6));
    return (int)(w * 64.0f);
}

__global__ void k_idx(const float* __restrict__ p){
    int i = blockIdx.x*256 + threadIdx.x;
    if(i >= BN) return;
    float x = p[i*3+0], y = p[i*3+1], z = p[i*3+2];
    int bx = binof(x), by = binof(y), bz = binof(z);
    g_idx[0*BN+i] = bx + 64*bz;
    g_idx[1*BN+i] = bx + 64*by;
    g_idx[2*BN+i] = by + 64*bz;
}

// ---------------- resblock weight prep ----------------
__global__ void k_wblk(const float* __restrict__ W0, const float* __restrict__ W1,
                       const float* __restrict__ Ws){
    int i = blockIdx.x*256 + threadIdx.x;
    if(i >= 3*20480) return;
    int m = i / 20480, r = i - m*20480;
    const float* src; int kc, n, s, K;
    if(r < 8192){ src = W0 + m*64*128; kc = r>>9; n = (r>>3)&63; s = r&7; K = 128; }
    else if(r < 12288){ int q = r-8192; src = W1 + m*64*64; kc = q>>9; n = (q>>3)&63; s = q&7; K = 64; }
    else { int q = r-12288; src = Ws + m*64*128; kc = q>>9; n = (q>>3)&63; s = q&7; K = 128; }
    int k = kc*8 + (s&1)*4 + (s>>1);
    g_wblk[i] = totf(src[n*K + k]);
}

// ---------------- fc_c weight prep ----------------
__global__ void k_wfcc(const float* __restrict__ Wc){
    int i = blockIdx.x*256 + threadIdx.x;
    if(i >= 16384) return;
    int s = i & 7, n = (i>>3)&255, kc = i>>11;
    int k = kc*8 + (s&1)*4 + (s>>1);
    g_wfcc[i] = totf(Wc[n*64 + k]);
}

// ---------------- fused resblock + scatter epilogue, TF32 mma ----------------
// mode 0: x from fc_pos(p);   epilogue: store g_net + scatter binsum2[0]
// mode 1: x from [net|pool0]; epilogue: store g_net + scatter binsum2[1]
// mode 2: x from [net|pool1]; epilogue: scatter nsum/cnt3 (3 planes), NO g_net store
#define SM_BLOCK ((16384 + 8192 + 20480)*4)

__global__ void __launch_bounds__(256) k_block(int mode, const float* __restrict__ p,
                        const float* __restrict__ fcW, const float* __restrict__ fcb,
                        const float* __restrict__ b0g, const float* __restrict__ b1g)
{
    extern __shared__ float sm[];
    float* x_s  = sm;              // [16 kc][128 pt][8]
    float* h_s  = sm + 16384;      // [8 kc][128 pt][8]
    float* wall = sm + 24576;
    float* w0_s = wall;
    float* w1_s = wall + 8192;
    float* ws_s = wall + 12288;
    unsigned wall_u = (unsigned)__cvta_generic_to_shared(wall);

    int t = threadIdx.x;
    int lane = t & 31, w = t >> 5;
    int wm = w & 3, wn = w >> 2;
    int q = lane >> 2, c = lane & 3;
    int s0 = (c < 2) ? 4*c     : 4*c - 7;
    int s1 = (c < 2) ? 4*c + 2 : 4*c - 5;

    int b = blockIdx.x / NT2, tile = blockIdx.x % NT2;
    int pt0 = tile*128;
    int npts = min(128, NP - pt0);
    int gbase = b*NP + pt0;

    {
        const float* wsrc = g_wblk + mode*20480;
        for(int e=t; e<5120; e+=256)
            cpa(wall_u + (unsigned)e*16, wsrc + e*4, 16);
        CP_COMMIT;
    }

    // stage x tile
    if(mode == 0){
        for(int e=t; e<4096; e+=256){
            int pt = e>>5, g = e&31;
            int kc = g>>1, half = g&1;
            int kb = kc*8 + half*4;
            float* d = &x_s[kc*1024 + pt*8 + half];
            if(pt < npts){
                int gp = (gbase + pt)*3;
                float px = p[gp], py = p[gp+1], pz = p[gp+2];
                #pragma unroll
                for(int i2=0;i2<4;i2++){
                    int j = kb + i2;
                    float v = fcb[j] + px*fcW[j*3] + py*fcW[j*3+1] + pz*fcW[j*3+2];
                    d[2*i2] = totf(v);
                }
            } else {
                d[0]=0.f; d[2]=0.f; d[4]=0.f; d[6]=0.f;
            }
        }
    } else {
        const float* bs   = g_binsum2 + ((mode-1)&1)*(BATCH*R2*HID);
        const float* bcnt = g_bincnt2 + ((mode-1)&1)*(BATCH*R2);
        for(int e=t; e<4096; e+=256){
            int pt = e>>5, g = e&31;
            int kc = g>>1, half = g&1;
            float4 v = make_float4(0.f,0.f,0.f,0.f);
            if(pt < npts){
                int gi = gbase + pt;
                if(kc < 8) v = *(const float4*)&g_net[gi*HID + kc*8 + half*4];
                else {
                    int row = b*R2 + g_idx[gi];
                    float inv = 1.0f / fmaxf(bcnt[row], 1.0f);
                    v = *(const float4*)&bs[row*HID + (kc-8)*8 + half*4];
                    v.x*=inv; v.y*=inv; v.z*=inv; v.w*=inv;
                }
            }
            float* d = &x_s[kc*1024 + pt*8 + half];
            d[0]=totf(v.x); d[2]=totf(v.y); d[4]=totf(v.z); d[6]=totf(v.w);
        }
    }
    CP_WAIT0;
    __syncthreads();

    int rb = wm*32;

    // GEMM1: h = relu(x @ W0^T + b0)
    float aH[2][4][4];
    #pragma unroll
    for(int mt=0;mt<2;mt++)
        #pragma unroll
        for(int nt=0;nt<4;nt++){ aH[mt][nt][0]=aH[mt][nt][1]=aH[mt][nt][2]=aH[mt][nt][3]=0.f; }
    #pragma unroll 4
    for(int kc=0; kc<16; kc++){
        uint2 a[2][2];
        #pragma unroll
        for(int mt=0;mt<2;mt++){
            a[mt][0] = *(const uint2*)&x_s[kc*1024 + (rb+mt*16+q)*8 + 2*c];
            a[mt][1] = *(const uint2*)&x_s[kc*1024 + (rb+mt*16+q+8)*8 + 2*c];
        }
        #pragma unroll
        for(int nt=0; nt<4; nt++){
            uint2 bb = *(const uint2*)&w0_s[kc*512 + (wn*32 + nt*8 + q)*8 + 2*c];
            mma8(aH[0][nt], a[0][0], a[0][1], bb);
            mma8(aH[1][nt], a[1][0], a[1][1], bb);
        }
    }
    #pragma unroll
    for(int nt=0; nt<4; nt++){
        int j0 = wn*32 + nt*8 + 2*c;
        float2 bb = *(const float2*)&b0g[j0];
        float* dl = &h_s[(j0>>3)*1024];
        #pragma unroll
        for(int mt=0;mt<2;mt++){
            int r0m = rb + mt*16 + q, r1m = r0m + 8;
            dl[r0m*8 + s0] = totf(fmaxf(aH[mt][nt][0]+bb.x, 0.f));
            dl[r0m*8 + s1] = totf(fmaxf(aH[mt][nt][1]+bb.y, 0.f));
            dl[r1m*8 + s0] = totf(fmaxf(aH[mt][nt][2]+bb.x, 0.f));
            dl[r1m*8 + s1] = totf(fmaxf(aH[mt][nt][3]+bb.y, 0.f));
        }
    }
    __syncthreads();

    // GEMM2: dx = relu(h @ W1^T + b1)
    float aD[2][4][4];
    #pragma unroll
    for(int mt=0;mt<2;mt++)
        #pragma unroll
        for(int nt=0;nt<4;nt++){ aD[mt][nt][0]=aD[mt][nt][1]=aD[mt][nt][2]=aD[mt][nt][3]=0.f; }
    #pragma unroll 4
    for(int kc=0; kc<8; kc++){
        uint2 a[2][2];
        #pragma unroll
        for(int mt=0;mt<2;mt++){
            a[mt][0] = *(const uint2*)&h_s[kc*1024 + (rb+mt*16+q)*8 + 2*c];
            a[mt][1] = *(const uint2*)&h_s[kc*1024 + (rb+mt*16+q+8)*8 + 2*c];
        }
        #pragma unroll
        for(int nt=0; nt<4; nt++){
            uint2 bb = *(const uint2*)&w1_s[kc*512 + (wn*32 + nt*8 + q)*8 + 2*c];
            mma8(aD[0][nt], a[0][0], a[0][1], bb);
            mma8(aD[1][nt], a[1][0], a[1][1], bb);
        }
    }
    #pragma unroll
    for(int nt=0; nt<4; nt++){
        int j0 = wn*32 + nt*8 + 2*c;
        float2 bb = *(const float2*)&b1g[j0];
        #pragma unroll
        for(int mt=0;mt<2;mt++){
            aD[mt][nt][0] = fmaxf(aD[mt][nt][0]+bb.x, 0.f);
            aD[mt][nt][1] = fmaxf(aD[mt][nt][1]+bb.y, 0.f);
            aD[mt][nt][2] = fmaxf(aD[mt][nt][2]+bb.x, 0.f);
            aD[mt][nt][3] = fmaxf(aD[mt][nt][3]+bb.y, 0.f);
        }
    }

    // GEMM3: out = x @ Ws^T + dx
    #pragma unroll 4
    for(int kc=0; kc<16; kc++){
        uint2 a[2][2];
        #pragma unroll
        for(int mt=0;mt<2;mt++){
            a[mt][0] = *(const uint2*)&x_s[kc*1024 + (rb+mt*16+q)*8 + 2*c];
            a[mt][1] = *(const uint2*)&x_s[kc*1024 + (rb+mt*16+q+8)*8 + 2*c];
        }
        #pragma unroll
        for(int nt=0; nt<4; nt++){
            uint2 bb = *(const uint2*)&ws_s[kc*512 + (wn*32 + nt*8 + q)*8 + 2*c];
            mma8(aD[0][nt], a[0][0], a[0][1], bb);
            mma8(aD[1][nt], a[1][0], a[1][1], bb);
        }
    }

    // ---------------- epilogue ----------------
    if(mode < 2){
        float* bs   = g_binsum2 + (mode&1)*(BATCH*R2*HID);
        float* bcnt = g_bincnt2 + (mode&1)*(BATCH*R2);
        // counts: one lane per row
        if(wn==0 && c==0){
            #pragma unroll
            for(int mt=0;mt<2;mt++){
                int r0m = rb+mt*16+q, r1m = r0m+8;
                if(r0m < npts) atomicAdd(&bcnt[b*R2 + g_idx[gbase+r0m]], 1.0f);
                if(r1m < npts) atomicAdd(&bcnt[b*R2 + g_idx[gbase+r1m]], 1.0f);
            }
        }
        int bin[2][2];
        #pragma unroll
        for(int mt=0;mt<2;mt++){
            int r0m = rb+mt*16+q, r1m = r0m+8;
            bin[mt][0] = (r0m < npts) ? (b*R2 + g_idx[gbase+r0m]) : -1;
            bin[mt][1] = (r1m < npts) ? (b*R2 + g_idx[gbase+r1m]) : -1;
        }
        #pragma unroll
        for(int nt=0; nt<4; nt++){
            int j0 = wn*32 + nt*8 + 2*c;
            #pragma unroll
            for(int mt=0;mt<2;mt++){
                int r0m = rb+mt*16+q, r1m = r0m+8;
                if(bin[mt][0] >= 0){
                    *(float2*)&g_net[(gbase+r0m)*HID + j0] = make_float2(aD[mt][nt][0], aD[mt][nt][1]);
                    atomicAdd(&bs[bin[mt][0]*HID + j0],   aD[mt][nt][0]);
                    atomicAdd(&bs[bin[mt][0]*HID + j0+1], aD[mt][nt][1]);
                }
                if(bin[mt][1] >= 0){
                    *(float2*)&g_net[(gbase+r1m)*HID + j0] = make_float2(aD[mt][nt][2], aD[mt][nt][3]);
                    atomicAdd(&bs[bin[mt][1]*HID + j0],   aD[mt][nt][2]);
                    atomicAdd(&bs[bin[mt][1]*HID + j0+1], aD[mt][nt][3]);
                }
            }
        }
    } else {
        // mode 2: scatter final net to 3 planes directly
        if(wn==0 && c==0){
            #pragma unroll
            for(int mt=0;mt<2;mt++)
                #pragma unroll
                for(int hh=0;hh<2;hh++){
                    int r = rb+mt*16+q+hh*8;
                    if(r < npts){
                        int gi = gbase + r;
                        #pragma unroll
                        for(int pl=0;pl<3;pl++)
                            atomicAdd(&g_cnt3[(pl*BATCH+b)*R2 + g_idx[pl*BN+gi]], 1.0f);
                    }
                }
        }
        int rowp[2][2][3];
        #pragma unroll
        for(int mt=0;mt<2;mt++)
            #pragma unroll
            for(int hh=0;hh<2;hh++){
                int r = rb+mt*16+q+hh*8;
                if(r < npts){
                    int gi = gbase + r;
                    #pragma unroll
                    for(int pl=0;pl<3;pl++)
                        rowp[mt][hh][pl] = (pl*BATCH+b)*R2 + g_idx[pl*BN+gi];
                } else {
                    rowp[mt][hh][0]=rowp[mt][hh][1]=rowp[mt][hh][2]=-1;
                }
            }
        #pragma unroll
        for(int nt=0; nt<4; nt++){
            int j0 = wn*32 + nt*8 + 2*c;
            #pragma unroll
            for(int mt=0;mt<2;mt++)
                #pragma unroll
                for(int hh=0;hh<2;hh++){
                    if(rowp[mt][hh][0] >= 0){
                        float v0 = aD[mt][nt][hh*2+0], v1 = aD[mt][nt][hh*2+1];
                        #pragma unroll
                        for(int pl=0;pl<3;pl++){
                            atomicAdd(&g_nsum[rowp[mt][hh][pl]*HID + j0],   v0);
                            atomicAdd(&g_nsum[rowp[mt][hh][pl]*HID + j0+1], v1);
                        }
                    }
                }
        }
    }
}

// ---------------- bin GEMM fc_c (TF32 mma) ----------------
#define SM_FCC ((4096 + 16384)*4)
__global__ void __launch_bounds__(256) k_fcc_bins(const float* __restrict__ bc){
    extern __shared__ float sm[];
    float* x_s = sm;             // [8kc][64pt][8]
    float* w_s = sm + 4096;      // [8kc][256n][8]
    unsigned ws_u = (unsigned)__cvta_generic_to_shared(w_s);
    int t = threadIdx.x;
    int lane = t & 31, w = t >> 5;
    int wm = w & 1, wn = w >> 1;
    int q = lane >> 2, c = lane & 3;
    int r0 = blockIdx.x*64;

    for(int e=t; e<4096; e+=256)
        cpa(ws_u + (unsigned)e*16, g_wfcc + e*4, 16);
    CP_COMMIT;

    for(int e=t; e<1024; e+=256){
        int pt = e>>4, g = e&15;
        int kc = g>>1, half = g&1;
        int row = r0 + pt;
        float inv = 1.0f / fmaxf(g_cnt3[row], 1.0f);
        float4 v = *(const float4*)&g_nsum[row*HID + kc*8 + half*4];
        float* d = &x_s[kc*512 + pt*8 + half];
        d[0]=totf(v.x*inv); d[2]=totf(v.y*inv); d[4]=totf(v.z*inv); d[6]=totf(v.w*inv);
    }
    CP_WAIT0;
    __syncthreads();

    int rb = wm*32;
    float acc[2][8][4];
    #pragma unroll
    for(int mt=0;mt<2;mt++)
        #pragma unroll
        for(int nt=0;nt<8;nt++){ acc[mt][nt][0]=acc[mt][nt][1]=acc[mt][nt][2]=acc[mt][nt][3]=0.f; }
    #pragma unroll
    for(int kc=0; kc<8; kc++){
        uint2 a[2][2];
        #pragma unroll
        for(int mt=0;mt<2;mt++){
            a[mt][0] = *(const uint2*)&x_s[kc*512 + (rb+mt*16+q)*8 + 2*c];
            a[mt][1] = *(const uint2*)&x_s[kc*512 + (rb+mt*16+q+8)*8 + 2*c];
        }
        const float* wb = &w_s[kc*2048 + (wn*64 + q)*8 + 2*c];
        #pragma unroll
        for(int nt=0; nt<8; nt++){
            uint2 bb = *(const uint2*)&wb[nt*64];
            mma8(acc[0][nt], a[0][0], a[0][1], bb);
            mma8(acc[1][nt], a[1][0], a[1][1], bb);
        }
    }

    const int iperm[8] = {0,2,4,6,1,3,5,7};
    #pragma unroll
    for(int nt=0; nt<8; nt++){
        int j0 = wn*64 + nt*8 + 2*c;
        float2 bb = *(const float2*)&bc[j0];
        #pragma unroll
        for(int mt=0;mt<2;mt++){
            #pragma unroll
            for(int half=0; half<2; half++){
                int r = rb + mt*16 + q + half*8;
                int row = r0 + r;
                float gate = (g_cnt3[row] > 0.f) ? 1.f : 0.f;
                float* d = &g_fea[row*FD + (j0 & ~7)];
                d[iperm[2*c]]   = totf(gate*(acc[mt][nt][half*2+0]+bb.x));
                d[iperm[2*c+1]] = totf(gate*(acc[mt][nt][half*2+1]+bb.y));
            }
        }
    }
}

// ---------------- conv weight prep ----------------
__global__ void k_wtrans(const float* __restrict__ Wa, const float* __restrict__ Wb){
    int i = blockIdx.x*256 + threadIdx.x;
    if(i >= 2*2304*FD) return;
    int cI = i / (2304*FD);
    int rem = i - cI*(2304*FD);
    int j  = rem & 7;
    int r2 = rem >> 3;
    int oc = r2 & 255;
    int r3 = r2 >> 8;
    int kk = r3 % 9, ch = r3 / 9;
    const int perm[8] = {0,4,1,5,2,6,3,7};
    int ic = ch*8 + perm[j];
    const float* W = cI ? Wb : Wa;
    g_wt[i] = totf(W[oc*2304 + ic*9 + kk]);
}

// ---------------- 3x3 conv 256->256, TF32 mma, cp.async, 2 CTA/SM ----------------
#define SM_CONV ((2*2112 + 2*9216)*4)

__global__ void __launch_bounds__(256, 2) k_conv(
        const float* __restrict__ in, float* __restrict__ out,
        const float* __restrict__ wt, const float* __restrict__ bias, int permout)
{
    extern __shared__ float sm[];
    float* ibuf = sm;
    float* wbuf = sm + 2*2112;
    unsigned ib_u = (unsigned)__cvta_generic_to_shared(ibuf);
    unsigned wb_u = (unsigned)__cvta_generic_to_shared(wbuf);
    int t = threadIdx.x;
    int lane = t & 31, w = t >> 5;
    int wm = w & 3, wn = w >> 2;
    int q = lane >> 2, c = lane & 3;

    int ocb = blockIdx.x & 1;
    int r = blockIdx.x >> 1;
    int rp = r & 31;
    int pb = r >> 5;
    const float* inp  = in  + pb*R2*FD;
    float*       outp = out + pb*R2*FD;
    int y0 = rp*2;
    int px_base = wm*32;

    float acc[2][8][4];
    #pragma unroll
    for(int mt=0; mt<2; mt++)
        #pragma unroll
        for(int nt=0; nt<8; nt++){
            acc[mt][nt][0]=0.f; acc[mt][nt][1]=0.f; acc[mt][nt][2]=0.f; acc[mt][nt][3]=0.f;
        }

    auto stage = [&](int ch, int buf){
        for(int e=t; e<528; e+=256){
            int pos = e>>1, half = e&1;
            int rr = pos/66, cc = pos - rr*66;
            int yy = y0 + rr - 1, xx = cc - 1;
            bool ok = (yy >= 0 && yy < 64 && (unsigned)xx < 64u);
            const float* src = inp + ((ok ? (yy*64+xx) : 0)*FD + ch*8 + half*4);
            cpa(ib_u + (unsigned)(buf*2112*4 + pos*32 + half*16), src, ok ? 16 : 0);
        }
        const float* wsrc = wt + (size_t)ch*18432 + ocb*1024;
        for(int e=t; e<2304; e+=256){
            int kk = e>>8, rem = e&255;
            cpa(wb_u + (unsigned)(buf*9216*4 + kk*4096 + rem*16),
                wsrc + kk*2048 + rem*4, 16);
        }
        CP_COMMIT;
    };

    stage(0, 0);
    for(int ch=0; ch<32; ch++){
        int cur = ch & 1;
        CP_WAIT0;
        __syncthreads();
        if(ch < 31) stage(ch+1, 1-cur);
        const float* in_s = ibuf + cur*2112;
        const float* w_s  = wbuf + cur*9216;
        #pragma unroll
        for(int kk=0; kk<9; kk++){
            int ky = kk/3, kx = kk - ky*3;
            uint2 a[2][2];
            #pragma unroll
            for(int mt=0; mt<2; mt++){
                int px0 = px_base + mt*16 + q;
                a[mt][0] = *(const uint2*)&in_s[(((px0>>6)+ky)*66 + (px0&63)+kx)*8 + 2*c];
                int px1 = px0 + 8;
                a[mt][1] = *(const uint2*)&in_s[(((px1>>6)+ky)*66 + (px1&63)+kx)*8 + 2*c];
            }
            const float* wb = &w_s[kk*1024 + (wn*64 + q)*8 + 2*c];
            #pragma unroll
            for(int nt=0; nt<8; nt++){
                uint2 b = *(const uint2*)&wb[nt*64];
                mma8(acc[0][nt], a[0][0], a[0][1], b);
                mma8(acc[1][nt], a[1][0], a[1][1], b);
            }
        }
        __syncthreads();
    }

    int o_base = ocb*128 + wn*64;
    const int iperm[8] = {0,2,4,6,1,3,5,7};
    #pragma unroll
    for(int nt=0; nt<8; nt++){
        int oc = o_base + nt*8 + 2*c;
        float2 bb = *(const float2*)&bias[oc];
        #pragma unroll
        for(int mt=0; mt<2; mt++){
            #pragma unroll
            for(int half=0; half<2; half++){
                int px = px_base + mt*16 + q + half*8;
                int y = y0 + (px>>6), x = px&63;
                float v0 = fmaxf(acc[mt][nt][half*2+0]+bb.x, 0.f);
                float v1 = fmaxf(acc[mt][nt][half*2+1]+bb.y, 0.f);
                float* d = &outp[(y*64+x)*FD];
                if(permout){
                    d[(oc & ~7) + iperm[2*c]]   = totf(v0);
                    d[(oc & ~7) + iperm[2*c+1]] = totf(v1);
                } else {
                    *(float2*)&d[oc] = make_float2(v0, v1);
                }
            }
        }
    }
}

// ---------------- bilinear grid sample over 3 planes, accumulate ----------------
__global__ void k_sample(const float* __restrict__ query, float* __restrict__ out){
    int gid = blockIdx.x*256 + threadIdx.x;
    int w = gid >> 5, lane = gid & 31;
    if(w >= BN) return;
    int b = w / NP;
    float q0 = query[w*3+0], q1 = query[w*3+1], q2 = query[w*3+2];
    float a0[4] = {0,0,0,0}, a1[4] = {0,0,0,0};
    #pragma unroll
    for(int pl=0; pl<3; pl++){
        float qa = (pl==2) ? q1 : q0;
        float qb = (pl==1) ? q1 : q2;
        float gx = qa*2.0f - 1.0f, gy = qb*2.0f - 1.0f;
        float x = ((gx + 1.0f)*64.0f - 1.0f)*0.5f;
        float y = ((gy + 1.0f)*64.0f - 1.0f)*0.5f;
        x = fminf(fmaxf(x, 0.0f), 63.0f);
        y = fminf(fmaxf(y, 0.0f), 63.0f);
        float x0f = floorf(x), y0f = floorf(y);
        int x0 = (int)x0f, y0 = (int)y0f;
        int x1 = min(x0+1, 63), y1 = min(y0+1, 63);
        float wx = x - x0f, wy = y - y0f;
        const float* f = &g_fec[(pl*BATCH + b)*R2*FD];
        float ww[4] = {(1.f-wx)*(1.f-wy), wx*(1.f-wy), (1.f-wx)*wy, wx*wy};
        int pix[4] = {y0*64+x0, y0*64+x1, y1*64+x0, y1*64+x1};
        #pragma unroll
        for(int tp=0; tp<4; tp++){
            const float* base = f + pix[tp]*FD;
            float4 v0 = *(const float4*)&base[lane*4];
            float4 v1 = *(const float4*)&base[128 + lane*4];
            float g = ww[tp];
            a0[0]+=g*v0.x; a0[1]+=g*v0.y; a0[2]+=g*v0.z; a0[3]+=g*v0.w;
            a1[0]+=g*v1.x; a1[1]+=g*v1.y; a1[2]+=g*v1.z; a1[3]+=g*v1.w;
        }
    }
    float* ob = &out[w*FD];
    *(float4*)&ob[lane*4]       = make_float4(a0[0],a0[1],a0[2],a0[3]);
    *(float4*)&ob[128+lane*4]   = make_float4(a1[0],a1[1],a1[2],a1[3]);
}

// ---------------- launch ----------------
extern "C" void kernel_launch(void* const* d_in, const int* in_sizes, int n_in,
                              void* d_out, int out_size)
{
    const float* p    = (const float*)d_in[0];
    const float* qry  = (const float*)d_in[1];
    const float* fcW  = (const float*)d_in[2];
    const float* fcb  = (const float*)d_in[3];
    const float* W0   = (const float*)d_in[4];
    const float* b0   = (const float*)d_in[5];
    const float* W1   = (const float*)d_in[6];
    const float* b1   = (const float*)d_in[7];
    const float* Ws   = (const float*)d_in[8];
    const float* Wc   = (const float*)d_in[9];
    const float* bc   = (const float*)d_in[10];
    const float* C1W  = (const float*)d_in[11];
    const float* C1b  = (const float*)d_in[12];
    const float* C2W  = (const float*)d_in[13];
    const float* C2b  = (const float*)d_in[14];
    float* out = (float*)d_out;

    cudaFuncSetAttribute(k_block,    cudaFuncAttributeMaxDynamicSharedMemorySize, SM_BLOCK);
    cudaFuncSetAttribute(k_fcc_bins, cudaFuncAttributeMaxDynamicSharedMemorySize, SM_FCC);
    cudaFuncSetAttribute(k_conv,     cudaFuncAttributeMaxDynamicSharedMemorySize, SM_CONV);

    void *binsum2_p, *bincnt2_p, *nsum_p, *cnt3_p, *fea_p, *feb_p, *fec_p, *wt_p;
    cudaGetSymbolAddress(&binsum2_p, g_binsum2);
    cudaGetSymbolAddress(&bincnt2_p, g_bincnt2);
    cudaGetSymbolAddress(&nsum_p,    g_nsum);
    cudaGetSymbolAddress(&cnt3_p,    g_cnt3);
    cudaGetSymbolAddress(&fea_p,     g_fea);
    cudaGetSymbolAddress(&feb_p,     g_feb);
    cudaGetSymbolAddress(&fec_p,     g_fec);
    cudaGetSymbolAddress(&wt_p,      g_wt);

    k_idx<<<(BN+255)/256, 256>>>(p);
    k_wtrans<<<(2*2304*FD)/256, 256>>>(C1W, C2W);
    k_wblk<<<(3*20480+255)/256, 256>>>(W0, W1, Ws);
    k_wfcc<<<16384/256, 256>>>(Wc);

    cudaMemsetAsync(binsum2_p, 0, (size_t)2*BATCH*R2*HID*4);
    cudaMemsetAsync(bincnt2_p, 0, (size_t)2*BATCH*R2*4);
    cudaMemsetAsync(nsum_p,    0, (size_t)NBROW*HID*4);
    cudaMemsetAsync(cnt3_p,    0, (size_t)NBROW*4);

    k_block<<<BATCH*NT2, 256, SM_BLOCK>>>(0, p, fcW, fcb, b0, b1);
    k_block<<<BATCH*NT2, 256, SM_BLOCK>>>(1, p, fcW, fcb, b0 + HID, b1 + HID);
    k_block<<<BATCH*NT2, 256, SM_BLOCK>>>(2, p, fcW, fcb, b0 + 2*HID, b1 + 2*HID);

    k_fcc_bins<<<NBROW/64, 256, SM_FCC>>>(bc);

    k_conv<<<12*32*2, 256, SM_CONV>>>((const float*)fea_p, (float*)feb_p,
                                      (const float*)wt_p,               C1b, 1);
    k_conv<<<12*32*2, 256, SM_CONV>>>((const float*)feb_p, (float*)fec_p,
                                      (const float*)wt_p + 2304*FD,     C2b, 0);

    k_sample<<<(BN*32)/256, 256>>>(qry, out);
}

// round 9
// speedup vs baseline: 3.8725x; 1.0756x over previous
#include <cuda_runtime.h>

#define BATCH 4
#define NP 30000
#define BN (BATCH*NP)
#define HID 64
#define FD 256
#define R2 4096
#define NT 469   /* ceil(NP/64) */
#define NBROW (3*BATCH*R2)

// ---------------- scratch (no allocation allowed) ----------------
__device__ float g_net[BN*HID];
__device__ int   g_idx[3*BN];
__device__ float g_binsum2[2*BATCH*R2*HID];   // ping-pong raw bin sums (xz pooling)
__device__ float g_bincnt2[2*BATCH*R2];
__device__ float g_nsum[NBROW*HID];
__device__ float g_cnt3[NBROW];
__device__ __align__(128) float g_fea[NBROW*FD];     // conv1 in  (permuted tf32)
__device__ __align__(128) float g_feb[NBROW*FD];     // conv1 out (permuted tf32)
__device__ __align__(128) float g_fec[NBROW*FD];     // conv2 out (natural fp32)
__device__ __align__(128) float g_wt[2*2304*FD];     // conv tf32 wt
__device__ __align__(128) float g_wblk[3*20480];     // resblock tf32 wt per mode
__device__ __align__(128) float g_wfcc[16384];       // fc_c tf32 wt [8kc][256n][8s]

// ---------------- helpers ----------------
__device__ __forceinline__ float totf(float x){
    unsigned u; asm("cvt.rna.tf32.f32 %0, %1;" : "=r"(u) : "f"(x));
    return __uint_as_float(u);
}
__device__ __forceinline__ void cpa(unsigned d, const void* s, int sz){
    asm volatile("cp.async.cg.shared.global [%0], [%1], 16, %2;" :: "r"(d), "l"(s), "r"(sz));
}
#define CP_COMMIT asm volatile("cp.async.commit_group;")
#define CP_WAIT0  asm volatile("cp.async.wait_group 0;")

__device__ __forceinline__ void mma8(float* d, uint2 ar0, uint2 ar1, uint2 b){
    asm volatile("mma.sync.aligned.m16n8k8.row.col.f32.tf32.tf32.f32 "
        "{%0,%1,%2,%3}, {%4,%5,%6,%7}, {%8,%9}, {%0,%1,%2,%3};"
        : "+f"(d[0]),"+f"(d[1]),"+f"(d[2]),"+f"(d[3])
        : "r"(ar0.x),"r"(ar1.x),"r"(ar0.y),"r"(ar1.y), "r"(b.x),"r"(b.y));
}

// ---------------- bin indices ----------------
__device__ __forceinline__ int binof(float v){
    const float DEN = (float)(1.0 + 0.1 + 1e-6);
    float w = (v + 0.5f) / DEN;
    w = fminf(fmaxf(w, 0.0f), (float)(1.0 - 1e-6));
    return (int)(w * 64.0f);
}

__global__ void k_idx(const float* __restrict__ p){
    int i = blockIdx.x*256 + threadIdx.x;
    if(i >= BN) return;
    float x = p[i*3+0], y = p[i*3+1], z = p[i*3+2];
    int bx = binof(x), by = binof(y), bz = binof(z);
    g_idx[0*BN+i] = bx + 64*bz;
    g_idx[1*BN+i] = bx + 64*by;
    g_idx[2*BN+i] = by + 64*bz;
}

// ---------------- resblock weight prep ----------------
__global__ void k_wblk(const float* __restrict__ W0, const float* __restrict__ W1,
                       const float* __restrict__ Ws){
    int i = blockIdx.x*256 + threadIdx.x;
    if(i >= 3*20480) return;
    int m = i / 20480, r = i - m*20480;
    const float* src; int kc, n, s, K;
    if(r < 8192){ src = W0 + m*64*128; kc = r>>9; n = (r>>3)&63; s = r&7; K = 128; }
    else if(r < 12288){ int q = r-8192; src = W1 + m*64*64; kc = q>>9; n = (q>>3)&63; s = q&7; K = 64; }
    else { int q = r-12288; src = Ws + m*64*128; kc = q>>9; n = (q>>3)&63; s = q&7; K = 128; }
    int k = kc*8 + (s&1)*4 + (s>>1);
    g_wblk[i] = totf(src[n*K + k]);
}

// ---------------- fc_c weight prep ----------------
__global__ void k_wfcc(const float* __restrict__ Wc){
    int i = blockIdx.x*256 + threadIdx.x;
    if(i >= 16384) return;
    int s = i & 7, n = (i>>3)&255, kc = i>>11;
    int k = kc*8 + (s&1)*4 + (s>>1);
    g_wfcc[i] = totf(Wc[n*64 + k]);
}

// ---------------- fused resblock + scatter epilogue, TF32 mma, 64-pt tiles, 2 CTA/SM ----------------
// smem: region X [16kc][64pt][8] = 8192 floats (h aliases first 4096 after pass 1)
//       region W: w0 (8192) -> later w1 (4096) at offset 0; ws (8192) at offset 8192
#define SM_BLOCK ((8192 + 16384)*4)

__global__ void __launch_bounds__(256, 2) k_block(int mode, const float* __restrict__ p,
                        const float* __restrict__ fcW, const float* __restrict__ fcb,
                        const float* __restrict__ b0g, const float* __restrict__ b1g)
{
    extern __shared__ float sm[];
    float* x_s  = sm;              // [16 kc][64 pt][8]; h aliases [8kc][64][8]
    float* wA   = sm + 8192;       // w0 then w1
    float* ws_s = sm + 16384;      // ws
    unsigned wA_u = (unsigned)__cvta_generic_to_shared(wA);

    int t = threadIdx.x;
    int lane = t & 31, w = t >> 5;
    int wm = w & 3, wn = w >> 2;           // 4 M-warps x 2 N-warps
    int q = lane >> 2, c = lane & 3;
    int s0 = (c < 2) ? 4*c     : 4*c - 7;
    int s1 = (c < 2) ? 4*c + 2 : 4*c - 5;

    int b = blockIdx.x / NT, tile = blockIdx.x % NT;
    int pt0 = tile*64;
    int npts = min(64, NP - pt0);
    int gbase = b*NP + pt0;

    // stage w0 + ws
    {
        const float* wsrc = g_wblk + mode*20480;
        for(int e=t; e<4096; e+=256){
            const float* src = (e < 2048) ? (wsrc + e*4) : (wsrc + 12288 + (e-2048)*4);
            cpa(wA_u + (unsigned)e*16, src, 16);
        }
        CP_COMMIT;
    }

    // stage x tile: 64 pt x 16 kc x 2 half
    if(mode == 0){
        for(int e=t; e<2048; e+=256){
            int pt = e>>5, g = e&31;
            int kc = g>>1, half = g&1;
            int kb = kc*8 + half*4;
            float* d = &x_s[kc*512 + pt*8 + half];
            if(pt < npts){
                int gp = (gbase + pt)*3;
                float px = p[gp], py = p[gp+1], pz = p[gp+2];
                #pragma unroll
                for(int i2=0;i2<4;i2++){
                    int j = kb + i2;
                    float v = fcb[j] + px*fcW[j*3] + py*fcW[j*3+1] + pz*fcW[j*3+2];
                    d[2*i2] = totf(v);
                }
            } else {
                d[0]=0.f; d[2]=0.f; d[4]=0.f; d[6]=0.f;
            }
        }
    } else {
        const float* bs   = g_binsum2 + ((mode-1)&1)*(BATCH*R2*HID);
        const float* bcnt = g_bincnt2 + ((mode-1)&1)*(BATCH*R2);
        for(int e=t; e<2048; e+=256){
            int pt = e>>5, g = e&31;
            int kc = g>>1, half = g&1;
            float4 v = make_float4(0.f,0.f,0.f,0.f);
            if(pt < npts){
                int gi = gbase + pt;
                if(kc < 8) v = *(const float4*)&g_net[gi*HID + kc*8 + half*4];
                else {
                    int row = b*R2 + g_idx[gi];
                    float inv = 1.0f / fmaxf(bcnt[row], 1.0f);
                    v = *(const float4*)&bs[row*HID + (kc-8)*8 + half*4];
                    v.x*=inv; v.y*=inv; v.z*=inv; v.w*=inv;
                }
            }
            float* d = &x_s[kc*512 + pt*8 + half];
            d[0]=totf(v.x); d[2]=totf(v.y); d[4]=totf(v.z); d[6]=totf(v.w);
        }
    }
    CP_WAIT0;
    __syncthreads();

    int rb = wm*16;
    int r0 = rb + q, r1 = rb + q + 8;

    // PASS 1 (fused): aH = x@W0^T ; aS = x@Ws^T
    float aH[4][4], aS[4][4];
    #pragma unroll
    for(int nt=0;nt<4;nt++){
        aH[nt][0]=aH[nt][1]=aH[nt][2]=aH[nt][3]=0.f;
        aS[nt][0]=aS[nt][1]=aS[nt][2]=aS[nt][3]=0.f;
    }
    #pragma unroll 4
    for(int kc=0; kc<16; kc++){
        uint2 a0 = *(const uint2*)&x_s[kc*512 + r0*8 + 2*c];
        uint2 a1 = *(const uint2*)&x_s[kc*512 + r1*8 + 2*c];
        #pragma unroll
        for(int nt=0; nt<4; nt++){
            int off = kc*512 + (wn*32 + nt*8 + q)*8 + 2*c;
            uint2 b0v = *(const uint2*)&wA[off];
            uint2 bsv = *(const uint2*)&ws_s[off];
            mma8(aH[nt], a0, a1, b0v);
            mma8(aS[nt], a0, a1, bsv);
        }
    }
    __syncthreads();   // x_s and w0 now dead

    // write h into x_s alias; stage w1 over w0
    {
        const float* wsrc = g_wblk + mode*20480 + 8192;
        for(int e=t; e<1024; e+=256)
            cpa(wA_u + (unsigned)e*16, wsrc + e*4, 16);
        CP_COMMIT;
    }
    #pragma unroll
    for(int nt=0; nt<4; nt++){
        int j0 = wn*32 + nt*8 + 2*c;
        float2 bb = *(const float2*)&b0g[j0];
        float* dl = &x_s[(j0>>3)*512];
        dl[r0*8 + s0] = totf(fmaxf(aH[nt][0]+bb.x, 0.f));
        dl[r0*8 + s1] = totf(fmaxf(aH[nt][1]+bb.y, 0.f));
        dl[r1*8 + s0] = totf(fmaxf(aH[nt][2]+bb.x, 0.f));
        dl[r1*8 + s1] = totf(fmaxf(aH[nt][3]+bb.y, 0.f));
    }
    CP_WAIT0;
    __syncthreads();

    // PASS 2: aD = h @ W1^T
    float aD[4][4];
    #pragma unroll
    for(int nt=0;nt<4;nt++){ aD[nt][0]=aD[nt][1]=aD[nt][2]=aD[nt][3]=0.f; }
    #pragma unroll
    for(int kc=0; kc<8; kc++){
        uint2 a0 = *(const uint2*)&x_s[kc*512 + r0*8 + 2*c];
        uint2 a1 = *(const uint2*)&x_s[kc*512 + r1*8 + 2*c];
        #pragma unroll
        for(int nt=0; nt<4; nt++){
            uint2 bb = *(const uint2*)&wA[kc*512 + (wn*32 + nt*8 + q)*8 + 2*c];
            mma8(aD[nt], a0, a1, bb);
        }
    }
    #pragma unroll
    for(int nt=0; nt<4; nt++){
        int j0 = wn*32 + nt*8 + 2*c;
        float2 bb = *(const float2*)&b1g[j0];
        aD[nt][0] = fmaxf(aD[nt][0]+bb.x, 0.f) + aS[nt][0];
        aD[nt][1] = fmaxf(aD[nt][1]+bb.y, 0.f) + aS[nt][1];
        aD[nt][2] = fmaxf(aD[nt][2]+bb.x, 0.f) + aS[nt][2];
        aD[nt][3] = fmaxf(aD[nt][3]+bb.y, 0.f) + aS[nt][3];
    }

    // ---------------- epilogue ----------------
    if(mode < 2){
        float* bs   = g_binsum2 + (mode&1)*(BATCH*R2*HID);
        float* bcnt = g_bincnt2 + (mode&1)*(BATCH*R2);
        if(wn==0 && c==0){
            if(r0 < npts) atomicAdd(&bcnt[b*R2 + g_idx[gbase+r0]], 1.0f);
            if(r1 < npts) atomicAdd(&bcnt[b*R2 + g_idx[gbase+r1]], 1.0f);
        }
        int bin0 = (r0 < npts) ? (b*R2 + g_idx[gbase+r0]) : -1;
        int bin1 = (r1 < npts) ? (b*R2 + g_idx[gbase+r1]) : -1;
        #pragma unroll
        for(int nt=0; nt<4; nt++){
            int j0 = wn*32 + nt*8 + 2*c;
            if(bin0 >= 0){
                *(float2*)&g_net[(gbase+r0)*HID + j0] = make_float2(aD[nt][0], aD[nt][1]);
                atomicAdd(&bs[bin0*HID + j0],   aD[nt][0]);
                atomicAdd(&bs[bin0*HID + j0+1], aD[nt][1]);
            }
            if(bin1 >= 0){
                *(float2*)&g_net[(gbase+r1)*HID + j0] = make_float2(aD[nt][2], aD[nt][3]);
                atomicAdd(&bs[bin1*HID + j0],   aD[nt][2]);
                atomicAdd(&bs[bin1*HID + j0+1], aD[nt][3]);
            }
        }
    } else {
        if(wn==0 && c==0){
            #pragma unroll
            for(int hh=0;hh<2;hh++){
                int r = rb + q + hh*8;
                if(r < npts){
                    int gi = gbase + r;
                    #pragma unroll
                    for(int pl=0;pl<3;pl++)
                        atomicAdd(&g_cnt3[(pl*BATCH+b)*R2 + g_idx[pl*BN+gi]], 1.0f);
                }
            }
        }
        int rowp[2][3];
        #pragma unroll
        for(int hh=0;hh<2;hh++){
            int r = rb + q + hh*8;
            if(r < npts){
                int gi = gbase + r;
                #pragma unroll
                for(int pl=0;pl<3;pl++)
                    rowp[hh][pl] = (pl*BATCH+b)*R2 + g_idx[pl*BN+gi];
            } else {
                rowp[hh][0]=rowp[hh][1]=rowp[hh][2]=-1;
            }
        }
        #pragma unroll
        for(int nt=0; nt<4; nt++){
            int j0 = wn*32 + nt*8 + 2*c;
            #pragma unroll
            for(int hh=0;hh<2;hh++){
                if(rowp[hh][0] >= 0){
                    float v0 = aD[nt][hh*2+0], v1 = aD[nt][hh*2+1];
                    #pragma unroll
                    for(int pl=0;pl<3;pl++){
                        atomicAdd(&g_nsum[rowp[hh][pl]*HID + j0],   v0);
                        atomicAdd(&g_nsum[rowp[hh][pl]*HID + j0+1], v1);
                    }
                }
            }
        }
    }
}

// ---------------- bin GEMM fc_c (TF32 mma) ----------------
#define SM_FCC ((4096 + 16384)*4)
__global__ void __launch_bounds__(256) k_fcc_bins(const float* __restrict__ bc){
    extern __shared__ float sm[];
    float* x_s = sm;             // [8kc][64pt][8]
    float* w_s = sm + 4096;      // [8kc][256n][8]
    unsigned ws_u = (unsigned)__cvta_generic_to_shared(w_s);
    int t = threadIdx.x;
    int lane = t & 31, w = t >> 5;
    int wm = w & 1, wn = w >> 1;
    int q = lane >> 2, c = lane & 3;
    int r0b = blockIdx.x*64;

    for(int e=t; e<4096; e+=256)
        cpa(ws_u + (unsigned)e*16, g_wfcc + e*4, 16);
    CP_COMMIT;

    for(int e=t; e<1024; e+=256){
        int pt = e>>4, g = e&15;
        int kc = g>>1, half = g&1;
        int row = r0b + pt;
        float inv = 1.0f / fmaxf(g_cnt3[row], 1.0f);
        float4 v = *(const float4*)&g_nsum[row*HID + kc*8 + half*4];
        float* d = &x_s[kc*512 + pt*8 + half];
        d[0]=totf(v.x*inv); d[2]=totf(v.y*inv); d[4]=totf(v.z*inv); d[6]=totf(v.w*inv);
    }
    CP_WAIT0;
    __syncthreads();

    int rb = wm*32;
    float acc[2][8][4];
    #pragma unroll
    for(int mt=0;mt<2;mt++)
        #pragma unroll
        for(int nt=0;nt<8;nt++){ acc[mt][nt][0]=acc[mt][nt][1]=acc[mt][nt][2]=acc[mt][nt][3]=0.f; }
    #pragma unroll
    for(int kc=0; kc<8; kc++){
        uint2 a[2][2];
        #pragma unroll
        for(int mt=0;mt<2;mt++){
            a[mt][0] = *(const uint2*)&x_s[kc*512 + (rb+mt*16+q)*8 + 2*c];
            a[mt][1] = *(const uint2*)&x_s[kc*512 + (rb+mt*16+q+8)*8 + 2*c];
        }
        const float* wb = &w_s[kc*2048 + (wn*64 + q)*8 + 2*c];
        #pragma unroll
        for(int nt=0; nt<8; nt++){
            uint2 bb = *(const uint2*)&wb[nt*64];
            mma8(acc[0][nt], a[0][0], a[0][1], bb);
            mma8(acc[1][nt], a[1][0], a[1][1], bb);
        }
    }

    const int iperm[8] = {0,2,4,6,1,3,5,7};
    #pragma unroll
    for(int nt=0; nt<8; nt++){
        int j0 = wn*64 + nt*8 + 2*c;
        float2 bb = *(const float2*)&bc[j0];
        #pragma unroll
        for(int mt=0;mt<2;mt++){
            #pragma unroll
            for(int half=0; half<2; half++){
                int r = rb + mt*16 + q + half*8;
                int row = r0b + r;
                float gate = (g_cnt3[row] > 0.f) ? 1.f : 0.f;
                float* d = &g_fea[row*FD + (j0 & ~7)];
                d[iperm[2*c]]   = totf(gate*(acc[mt][nt][half*2+0]+bb.x));
                d[iperm[2*c+1]] = totf(gate*(acc[mt][nt][half*2+1]+bb.y));
            }
        }
    }
}

// ---------------- conv weight prep ----------------
__global__ void k_wtrans(const float* __restrict__ Wa, const float* __restrict__ Wb){
    int i = blockIdx.x*256 + threadIdx.x;
    if(i >= 2*2304*FD) return;
    int cI = i / (2304*FD);
    int rem = i - cI*(2304*FD);
    int j  = rem & 7;
    int r2 = rem >> 3;
    int oc = r2 & 255;
    int r3 = r2 >> 8;
    int kk = r3 % 9, ch = r3 / 9;
    const int perm[8] = {0,4,1,5,2,6,3,7};
    int ic = ch*8 + perm[j];
    const float* W = cI ? Wb : Wa;
    g_wt[i] = totf(W[oc*2304 + ic*9 + kk]);
}

// ---------------- 3x3 conv 256->256, TF32 mma, cp.async, 2 CTA/SM ----------------
#define SM_CONV ((2*2112 + 2*9216)*4)

__global__ void __launch_bounds__(256, 2) k_conv(
        const float* __restrict__ in, float* __restrict__ out,
        const float* __restrict__ wt, const float* __restrict__ bias, int permout)
{
    extern __shared__ float sm[];
    float* ibuf = sm;
    float* wbuf = sm + 2*2112;
    unsigned ib_u = (unsigned)__cvta_generic_to_shared(ibuf);
    unsigned wb_u = (unsigned)__cvta_generic_to_shared(wbuf);
    int t = threadIdx.x;
    int lane = t & 31, w = t >> 5;
    int wm = w & 3, wn = w >> 2;
    int q = lane >> 2, c = lane & 3;

    int ocb = blockIdx.x & 1;
    int r = blockIdx.x >> 1;
    int rp = r & 31;
    int pb = r >> 5;
    const float* inp  = in  + pb*R2*FD;
    float*       outp = out + pb*R2*FD;
    int y0 = rp*2;
    int px_base = wm*32;

    float acc[2][8][4];
    #pragma unroll
    for(int mt=0; mt<2; mt++)
        #pragma unroll
        for(int nt=0; nt<8; nt++){
            acc[mt][nt][0]=0.f; acc[mt][nt][1]=0.f; acc[mt][nt][2]=0.f; acc[mt][nt][3]=0.f;
        }

    auto stage = [&](int ch, int buf){
        for(int e=t; e<528; e+=256){
            int pos = e>>1, half = e&1;
            int rr = pos/66, cc = pos - rr*66;
            int yy = y0 + rr - 1, xx = cc - 1;
            bool ok = (yy >= 0 && yy < 64 && (unsigned)xx < 64u);
            const float* src = inp + ((ok ? (yy*64+xx) : 0)*FD + ch*8 + half*4);
            cpa(ib_u + (unsigned)(buf*2112*4 + pos*32 + half*16), src, ok ? 16 : 0);
        }
        const float* wsrc = wt + (size_t)ch*18432 + ocb*1024;
        for(int e=t; e<2304; e+=256){
            int kk = e>>8, rem = e&255;
            cpa(wb_u + (unsigned)(buf*9216*4 + kk*4096 + rem*16),
                wsrc + kk*2048 + rem*4, 16);
        }
        CP_COMMIT;
    };

    stage(0, 0);
    for(int ch=0; ch<32; ch++){
        int cur = ch & 1;
        CP_WAIT0;
        __syncthreads();
        if(ch < 31) stage(ch+1, 1-cur);
        const float* in_s = ibuf + cur*2112;
        const float* w_s  = wbuf + cur*9216;
        #pragma unroll
        for(int kk=0; kk<9; kk++){
            int ky = kk/3, kx = kk - ky*3;
            uint2 a[2][2];
            #pragma unroll
            for(int mt=0; mt<2; mt++){
                int px0 = px_base + mt*16 + q;
                a[mt][0] = *(const uint2*)&in_s[(((px0>>6)+ky)*66 + (px0&63)+kx)*8 + 2*c];
                int px1 = px0 + 8;
                a[mt][1] = *(const uint2*)&in_s[(((px1>>6)+ky)*66 + (px1&63)+kx)*8 + 2*c];
            }
            const float* wb = &w_s[kk*1024 + (wn*64 + q)*8 + 2*c];
            #pragma unroll
            for(int nt=0; nt<8; nt++){
                uint2 b = *(const uint2*)&wb[nt*64];
                mma8(acc[0][nt], a[0][0], a[0][1], b);
                mma8(acc[1][nt], a[1][0], a[1][1], b);
            }
        }
        __syncthreads();
    }

    int o_base = ocb*128 + wn*64;
    const int iperm[8] = {0,2,4,6,1,3,5,7};
    #pragma unroll
    for(int nt=0; nt<8; nt++){
        int oc = o_base + nt*8 + 2*c;
        float2 bb = *(const float2*)&bias[oc];
        #pragma unroll
        for(int mt=0; mt<2; mt++){
            #pragma unroll
            for(int half=0; half<2; half++){
                int px = px_base + mt*16 + q + half*8;
                int y = y0 + (px>>6), x = px&63;
                float v0 = fmaxf(acc[mt][nt][half*2+0]+bb.x, 0.f);
                float v1 = fmaxf(acc[mt][nt][half*2+1]+bb.y, 0.f);
                float* d = &outp[(y*64+x)*FD];
                if(permout){
                    d[(oc & ~7) + iperm[2*c]]   = totf(v0);
                    d[(oc & ~7) + iperm[2*c+1]] = totf(v1);
                } else {
                    *(float2*)&d[oc] = make_float2(v0, v1);
                }
            }
        }
    }
}

// ---------------- bilinear grid sample over 3 planes, accumulate ----------------
__global__ void k_sample(const float* __restrict__ query, float* __restrict__ out){
    int gid = blockIdx.x*256 + threadIdx.x;
    int w = gid >> 5, lane = gid & 31;
    if(w >= BN) return;
    int b = w / NP;
    float q0 = query[w*3+0], q1 = query[w*3+1], q2 = query[w*3+2];
    float a0[4] = {0,0,0,0}, a1[4] = {0,0,0,0};
    #pragma unroll
    for(int pl=0; pl<3; pl++){
        float qa = (pl==2) ? q1 : q0;
        float qb = (pl==1) ? q1 : q2;
        float gx = qa*2.0f - 1.0f, gy = qb*2.0f - 1.0f;
        float x = ((gx + 1.0f)*64.0f - 1.0f)*0.5f;
        float y = ((gy + 1.0f)*64.0f - 1.0f)*0.5f;
        x = fminf(fmaxf(x, 0.0f), 63.0f);
        y = fminf(fmaxf(y, 0.0f), 63.0f);
        float x0f = floorf(x), y0f = floorf(y);
        int x0 = (int)x0f, y0 = (int)y0f;
        int x1 = min(x0+1, 63), y1 = min(y0+1, 63);
        float wx = x - x0f, wy = y - y0f;
        const float* f = &g_fec[(pl*BATCH + b)*R2*FD];
        float ww[4] = {(1.f-wx)*(1.f-wy), wx*(1.f-wy), (1.f-wx)*wy, wx*wy};
        int pix[4] = {y0*64+x0, y0*64+x1, y1*64+x0, y1*64+x1};
        #pragma unroll
        for(int tp=0; tp<4; tp++){
            const float* base = f + pix[tp]*FD;
            float4 v0 = *(const float4*)&base[lane*4];
            float4 v1 = *(const float4*)&base[128 + lane*4];
            float g = ww[tp];
            a0[0]+=g*v0.x; a0[1]+=g*v0.y; a0[2]+=g*v0.z; a0[3]+=g*v0.w;
            a1[0]+=g*v1.x; a1[1]+=g*v1.y; a1[2]+=g*v1.z; a1[3]+=g*v1.w;
        }
    }
    float* ob = &out[w*FD];
    *(float4*)&ob[lane*4]       = make_float4(a0[0],a0[1],a0[2],a0[3]);
    *(float4*)&ob[128+lane*4]   = make_float4(a1[0],a1[1],a1[2],a1[3]);
}

// ---------------- launch ----------------
extern "C" void kernel_launch(void* const* d_in, const int* in_sizes, int n_in,
                              void* d_out, int out_size)
{
    const float* p    = (const float*)d_in[0];
    const float* qry  = (const float*)d_in[1];
    const float* fcW  = (const float*)d_in[2];
    const float* fcb  = (const float*)d_in[3];
    const float* W0   = (const float*)d_in[4];
    const float* b0   = (const float*)d_in[5];
    const float* W1   = (const float*)d_in[6];
    const float* b1   = (const float*)d_in[7];
    const float* Ws   = (const float*)d_in[8];
    const float* Wc   = (const float*)d_in[9];
    const float* bc   = (const float*)d_in[10];
    const float* C1W  = (const float*)d_in[11];
    const float* C1b  = (const float*)d_in[12];
    const float* C2W  = (const float*)d_in[13];
    const float* C2b  = (const float*)d_in[14];
    float* out = (float*)d_out;

    cudaFuncSetAttribute(k_block,    cudaFuncAttributeMaxDynamicSharedMemorySize, SM_BLOCK);
    cudaFuncSetAttribute(k_fcc_bins, cudaFuncAttributeMaxDynamicSharedMemorySize, SM_FCC);
    cudaFuncSetAttribute(k_conv,     cudaFuncAttributeMaxDynamicSharedMemorySize, SM_CONV);

    void *binsum2_p, *bincnt2_p, *nsum_p, *cnt3_p, *fea_p, *feb_p, *fec_p, *wt_p;
    cudaGetSymbolAddress(&binsum2_p, g_binsum2);
    cudaGetSymbolAddress(&bincnt2_p, g_bincnt2);
    cudaGetSymbolAddress(&nsum_p,    g_nsum);
    cudaGetSymbolAddress(&cnt3_p,    g_cnt3);
    cudaGetSymbolAddress(&fea_p,     g_fea);
    cudaGetSymbolAddress(&feb_p,     g_feb);
    cudaGetSymbolAddress(&fec_p,     g_fec);
    cudaGetSymbolAddress(&wt_p,      g_wt);

    k_idx<<<(BN+255)/256, 256>>>(p);
    k_wblk<<<(3*20480+255)/256, 256>>>(W0, W1, Ws);

    cudaMemsetAsync(binsum2_p, 0, (size_t)2*BATCH*R2*HID*4);
    cudaMemsetAsync(bincnt2_p, 0, (size_t)2*BATCH*R2*4);
    cudaMemsetAsync(nsum_p,    0, (size_t)NBROW*HID*4);
    cudaMemsetAsync(cnt3_p,    0, (size_t)NBROW*4);

    k_block<<<BATCH*NT, 256, SM_BLOCK>>>(0, p, fcW, fcb, b0, b1);
    k_block<<<BATCH*NT, 256, SM_BLOCK>>>(1, p, fcW, fcb, b0 + HID, b1 + HID);
    k_block<<<BATCH*NT, 256, SM_BLOCK>>>(2, p, fcW, fcb, b0 + 2*HID, b1 + 2*HID);

    k_wfcc<<<16384/256, 256>>>(Wc);
    k_fcc_bins<<<NBROW/64, 256, SM_FCC>>>(bc);

    k_wtrans<<<(2*2304*FD)/256, 256>>>(C1W, C2W);
    k_conv<<<12*32*2, 256, SM_CONV>>>((const float*)fea_p, (float*)feb_p,
                                      (const float*)wt_p,               C1b, 1);
    k_conv<<<12*32*2, 256, SM_CONV>>>((const float*)feb_p, (float*)fec_p,
                                      (const float*)wt_p + 2304*FD,     C2b, 0);

    k_sample<<<(BN*32)/256, 256>>>(qry, out);
}